// round 5
// baseline (speedup 1.0000x reference)
#include <cuda_runtime.h>
#include <cuda_bf16.h>
#include <cstdint>
#include <cstddef>

// ---------------------------------------------------------------------------
// StyledMLP: 3 chained modulated 1x1 convs (B=16, C=256, N=16384, S=512)
// Legacy mma.sync bf16 (tcgen05 rejected: harness emits compute_103 PTX).
// 3-term split-bf16 (hi*hi + hi*lo + lo*hi), fp32 accumulate.
// R4: term-major MMA ordering + 3-stage cp.async pipeline, 1 barrier/chunk.
// ---------------------------------------------------------------------------

#define CB   16
#define CC   256
#define NN   16384
#define SS   512

#define BM 128
#define BN 128
#define BK 32

// scratch (allocation-free rule: __device__ globals)
__device__ __nv_bfloat16 g_Xh0[(size_t)CB * CC * NN];
__device__ __nv_bfloat16 g_Xl0[(size_t)CB * CC * NN];
__device__ __nv_bfloat16 g_Xh1[(size_t)CB * CC * NN];
__device__ __nv_bfloat16 g_Xl1[(size_t)CB * CC * NN];
__device__ __nv_bfloat16 g_Whi[3 * CB * CC * CC];
__device__ __nv_bfloat16 g_Wlo[3 * CB * CC * CC];
__device__ float         g_style[3 * CB * CC];

// ---------------------------------------------------------------------------
// PTX helpers
// ---------------------------------------------------------------------------
__device__ __forceinline__ void cp16(void* sdst, const void* gsrc) {
    unsigned a = (unsigned)__cvta_generic_to_shared(sdst);
    asm volatile("cp.async.cg.shared.global [%0], [%1], 16;\n" :: "r"(a), "l"(gsrc));
}
__device__ __forceinline__ void cp_commit() {
    asm volatile("cp.async.commit_group;\n" ::: "memory");
}
__device__ __forceinline__ void ldsm4(uint32_t* r, const void* p) {
    unsigned a = (unsigned)__cvta_generic_to_shared(p);
    asm volatile("ldmatrix.sync.aligned.m8n8.x4.shared.b16 {%0,%1,%2,%3}, [%4];\n"
                 : "=r"(r[0]), "=r"(r[1]), "=r"(r[2]), "=r"(r[3]) : "r"(a));
}
__device__ __forceinline__ void ldsm4t(uint32_t* r, const void* p) {
    unsigned a = (unsigned)__cvta_generic_to_shared(p);
    asm volatile("ldmatrix.sync.aligned.m8n8.x4.trans.shared.b16 {%0,%1,%2,%3}, [%4];\n"
                 : "=r"(r[0]), "=r"(r[1]), "=r"(r[2]), "=r"(r[3]) : "r"(a));
}
__device__ __forceinline__ uint32_t packbf(float lo, float hi) {  // low 16 = lo
    uint32_t r;
    asm("cvt.rn.bf16x2.f32 %0, %1, %2;" : "=r"(r) : "f"(hi), "f"(lo));
    return r;
}
__device__ __forceinline__ void mma16816(float* c, const uint32_t* a, uint32_t b0, uint32_t b1) {
    asm volatile("mma.sync.aligned.m16n8k16.row.col.f32.bf16.bf16.f32 "
                 "{%0,%1,%2,%3}, {%4,%5,%6,%7}, {%8,%9}, {%0,%1,%2,%3};\n"
                 : "+f"(c[0]), "+f"(c[1]), "+f"(c[2]), "+f"(c[3])
                 : "r"(a[0]), "r"(a[1]), "r"(a[2]), "r"(a[3]), "r"(b0), "r"(b1));
}
__device__ __forceinline__ float warp_sum(float v) {
    #pragma unroll
    for (int o = 16; o; o >>= 1) v += __shfl_xor_sync(0xffffffffu, v, o);
    return v;
}

// ---------------------------------------------------------------------------
// Modulation (coalesced, warp-cooperative)
// ---------------------------------------------------------------------------
struct ModArgs {
    const float* w[3];
    const float* mw[3];
    const float* mb[3];
};

__global__ void style_kernel(const float* __restrict__ z, ModArgs args) {
    int layer = blockIdx.x, b = blockIdx.y;
    int tid = threadIdx.x, warp = tid >> 5, lane = tid & 31;
    __shared__ float zs[SS];
    for (int i = tid; i < SS; i += 256) zs[i] = z[(size_t)b * SS + i];
    __syncthreads();

    const float* mw = args.mw[layer];
    const float* mb = args.mb[layer];
    for (int c = warp; c < CC; c += 8) {
        const float* row = mw + (size_t)c * SS;
        float s = 0.f;
        #pragma unroll
        for (int j = 0; j < SS / 32; j++)
            s = fmaf(row[lane + 32 * j], zs[lane + 32 * j], s);
        s = warp_sum(s);
        if (lane == 0)
            g_style[((size_t)layer * CB + b) * CC + c] =
                s * 0.04419417382415922f + mb[c];
    }
}

__global__ void modw_kernel(ModArgs args) {
    int layer = blockIdx.x, b = blockIdx.y;
    int tid = threadIdx.x, warp = tid >> 5, lane = tid & 31;
    __shared__ float st[CC];
    for (int i = tid; i < CC; i += 256)
        st[i] = g_style[((size_t)layer * CB + b) * CC + i];
    __syncthreads();

    const float* w = args.w[layer];
    __nv_bfloat16* oh = g_Whi + ((size_t)(layer * CB + b)) * CC * CC;
    __nv_bfloat16* ol = g_Wlo + ((size_t)(layer * CB + b)) * CC * CC;

    for (int r = warp; r < CC; r += 8) {
        const float* wr = w + (size_t)r * CC;
        float s2 = 0.f;
        #pragma unroll
        for (int j = 0; j < CC / 32; j++) {
            float v = wr[lane + 32 * j] * st[lane + 32 * j];
            s2 = fmaf(v, v, s2);
        }
        s2 = warp_sum(s2);
        float ss = s2 * (0.0625f * 0.0625f) + 1e-8f;
        float d = rsqrtf(ss);
        d = d * (1.5f - 0.5f * ss * d * d);
        float scale = 0.0625f * d;
        #pragma unroll
        for (int j = 0; j < CC / 32; j++) {
            int i = lane + 32 * j;
            float v = wr[i] * st[i] * scale;
            __nv_bfloat16 h = __float2bfloat16(v);
            oh[(size_t)r * CC + i] = h;
            ol[(size_t)r * CC + i] = __float2bfloat16(v - __bfloat162float(h));
        }
    }
}

// ---------------------------------------------------------------------------
// GEMM smem: 3 stages of 37888 B:
//   [0,10240)     W hi : 128 x 40 bf16 (32 used + 8 pad)
//   [10240,20480) W lo
//   [20480,...)   X: fp32 staging 32x132 f32 (16896)  OR  bf16 hi/lo 32x136 x2
// ---------------------------------------------------------------------------
#define WPITCH 40
#define STG_PITCHF 132
#define XP 136
#define XPLANE 8704
#define PS 37888
#define SMEM_BYTES (3 * PS)

template<int IN_M>
__device__ __forceinline__ void load_stage(char* sm, int stage,
                                           const __nv_bfloat16* gWh,
                                           const __nv_bfloat16* gWl,
                                           const float* Xf,
                                           const __nv_bfloat16* Xh,
                                           const __nv_bfloat16* Xl,
                                           int k0, int n0, int tid) {
    char* base = sm + stage * PS;
    #pragma unroll
    for (int i = 0; i < 2; i++) {                 // W hi+lo: 128x32 bf16
        int c = tid + i * 256;
        int row = c >> 2, cc = c & 3;
        cp16(base + (row * WPITCH + cc * 8) * 2, gWh + (size_t)row * CC + k0 + cc * 8);
        cp16(base + 10240 + (row * WPITCH + cc * 8) * 2, gWl + (size_t)row * CC + k0 + cc * 8);
    }
    if (IN_M == 0) {
        #pragma unroll
        for (int i = 0; i < 4; i++) {             // X fp32: 32x128
            int c = tid + i * 256;
            int row = c >> 5, cc = c & 31;
            cp16(base + 20480 + row * (STG_PITCHF * 4) + cc * 16,
                 Xf + (size_t)(k0 + row) * NN + n0 + cc * 4);
        }
    } else {
        #pragma unroll
        for (int i = 0; i < 4; i++) {             // X bf16 hi+lo: 32x128 each
            int c = tid + i * 256;
            int plane = c >> 9;
            int cc5 = c & 511;
            int row = cc5 >> 4, cc = cc5 & 15;
            const __nv_bfloat16* src = (plane ? Xl : Xh) + (size_t)(k0 + row) * NN + n0 + cc * 8;
            cp16(base + 20480 + plane * XPLANE + (row * XP + cc * 8) * 2, src);
        }
    }
}

// ---------------------------------------------------------------------------
// GEMM. CTA 128x128, 8 warps (warp tile 64x32), K=256, 3-stage pipeline.
// ---------------------------------------------------------------------------
template<int IN_M, int OUT_M>
__global__ void __launch_bounds__(256, 2)
gemm_kernel(const float* __restrict__ xin, const float* __restrict__ bias,
            float* __restrict__ yout, int layer) {
    extern __shared__ __align__(128) char sm[];

    const __nv_bfloat16* Xh_in = (IN_M == 1) ? g_Xh0 : g_Xh1;
    const __nv_bfloat16* Xl_in = (IN_M == 1) ? g_Xl0 : g_Xl1;

    int b  = blockIdx.z;
    int m0 = blockIdx.y * BM;
    int n0 = blockIdx.x * BN;
    int tid  = threadIdx.x;
    int lane = tid & 31;
    int warp = tid >> 5;
    int wm = warp & 1;
    int wn = warp >> 1;

    const __nv_bfloat16* gWh = g_Whi + ((size_t)(layer * CB + b)) * CC * CC + (size_t)m0 * CC;
    const __nv_bfloat16* gWl = g_Wlo + ((size_t)(layer * CB + b)) * CC * CC + (size_t)m0 * CC;
    const float* Xf = (IN_M == 0) ? (xin + (size_t)b * CC * NN) : nullptr;
    const __nv_bfloat16* Xh = (IN_M == 0) ? nullptr : Xh_in + (size_t)b * CC * NN;
    const __nv_bfloat16* Xl = (IN_M == 0) ? nullptr : Xl_in + (size_t)b * CC * NN;

    float acc[4][4][4];
    #pragma unroll
    for (int i = 0; i < 4; i++)
        #pragma unroll
        for (int j = 0; j < 4; j++)
            #pragma unroll
            for (int k = 0; k < 4; k++) acc[i][j][k] = 0.f;

    load_stage<IN_M>(sm, 0, gWh, gWl, Xf, Xh, Xl, 0, n0, tid);
    cp_commit();
    load_stage<IN_M>(sm, 1, gWh, gWl, Xf, Xh, Xl, BK, n0, tid);
    cp_commit();

    #pragma unroll 1
    for (int ch = 0; ch < 8; ch++) {
        int stage = ch - (ch >= 6 ? 6 : (ch >= 3 ? 3 : 0));   // ch % 3
        if (ch < 7) asm volatile("cp.async.wait_group 1;\n" ::: "memory");
        else        asm volatile("cp.async.wait_group 0;\n" ::: "memory");
        __syncthreads();   // data for chunk ch visible; chunk ch-1 fully consumed

        if (ch + 2 < 8) {
            int ns = stage + 2 - (stage + 2 >= 3 ? 3 : 0);
            load_stage<IN_M>(sm, ns, gWh, gWl, Xf, Xh, Xl, (ch + 2) * BK, n0, tid);
            cp_commit();
        }

        char* base = sm + stage * PS;
        const __nv_bfloat16* Whi = (const __nv_bfloat16*)base;
        const __nv_bfloat16* Wlo = (const __nv_bfloat16*)(base + 10240);

        #pragma unroll
        for (int kk = 0; kk < BK; kk += 16) {
            uint32_t ah[4][4], al[4][4];
            #pragma unroll
            for (int mt = 0; mt < 4; mt++) {
                int row = wm * 64 + mt * 16 + (lane & 15);
                int col = kk + ((lane >> 4) << 3);
                ldsm4(ah[mt], &Whi[row * WPITCH + col]);
                ldsm4(al[mt], &Wlo[row * WPITCH + col]);
            }
            if (IN_M == 0) {
                const float* Xst = (const float*)(base + 20480);
                #pragma unroll
                for (int nt = 0; nt < 4; nt++) {
                    int n  = wn * 32 + nt * 8 + (lane >> 2);
                    int kb = kk + 2 * (lane & 3);
                    const float* xp = Xst + kb * STG_PITCHF + n;
                    float x0 = xp[0];
                    float x1 = xp[STG_PITCHF];
                    float x2 = xp[8 * STG_PITCHF];
                    float x3 = xp[9 * STG_PITCHF];
                    uint32_t bh0 = packbf(x0, x1);
                    uint32_t bh1 = packbf(x2, x3);
                    float h0 = __uint_as_float(bh0 << 16);
                    float h1 = __uint_as_float(bh0 & 0xffff0000u);
                    float h2 = __uint_as_float(bh1 << 16);
                    float h3 = __uint_as_float(bh1 & 0xffff0000u);
                    uint32_t bl0 = packbf(x0 - h0, x1 - h1);
                    uint32_t bl1 = packbf(x2 - h2, x3 - h3);
                    // term-major within nt: same-acc reuse distance 4
                    #pragma unroll
                    for (int mt = 0; mt < 4; mt++) mma16816(acc[mt][nt], ah[mt], bh0, bh1);
                    #pragma unroll
                    for (int mt = 0; mt < 4; mt++) mma16816(acc[mt][nt], ah[mt], bl0, bl1);
                    #pragma unroll
                    for (int mt = 0; mt < 4; mt++) mma16816(acc[mt][nt], al[mt], bh0, bh1);
                }
            } else {
                const __nv_bfloat16* sXh = (const __nv_bfloat16*)(base + 20480);
                const __nv_bfloat16* sXl = (const __nv_bfloat16*)(base + 20480 + XPLANE);
                uint32_t bh[2][4], bl[2][4];
                #pragma unroll
                for (int c2 = 0; c2 < 2; c2++) {
                    int k = kk + ((lane >> 3) & 1) * 8 + (lane & 7);
                    int n = wn * 32 + c2 * 16 + (lane >> 4) * 8;
                    ldsm4t(bh[c2], &sXh[k * XP + n]);
                    ldsm4t(bl[c2], &sXl[k * XP + n]);
                }
                // full term-major: same-acc reuse distance 16
                #pragma unroll
                for (int nt = 0; nt < 4; nt++) {
                    int c2 = nt >> 1, sub = (nt & 1) * 2;
                    #pragma unroll
                    for (int mt = 0; mt < 4; mt++)
                        mma16816(acc[mt][nt], ah[mt], bh[c2][sub], bh[c2][sub + 1]);
                }
                #pragma unroll
                for (int nt = 0; nt < 4; nt++) {
                    int c2 = nt >> 1, sub = (nt & 1) * 2;
                    #pragma unroll
                    for (int mt = 0; mt < 4; mt++)
                        mma16816(acc[mt][nt], ah[mt], bl[c2][sub], bl[c2][sub + 1]);
                }
                #pragma unroll
                for (int nt = 0; nt < 4; nt++) {
                    int c2 = nt >> 1, sub = (nt & 1) * 2;
                    #pragma unroll
                    for (int mt = 0; mt < 4; mt++)
                        mma16816(acc[mt][nt], al[mt], bh[c2][sub], bh[c2][sub + 1]);
                }
            }
        }
    }

    // epilogue: bias + leaky(0.2) * sqrt(2)
    const float S2 = 1.4142135623730951f;
    __nv_bfloat16* Yh = (OUT_M == 1) ? g_Xh0 : g_Xh1;
    __nv_bfloat16* Yl = (OUT_M == 1) ? g_Xl0 : g_Xl1;
    float* Yf = (OUT_M == 0) ? (yout + (size_t)b * CC * NN) : nullptr;
    if (OUT_M != 0) { Yh += (size_t)b * CC * NN; Yl += (size_t)b * CC * NN; }

    #pragma unroll
    for (int mt = 0; mt < 4; mt++) {
        int r0 = m0 + wm * 64 + mt * 16 + (lane >> 2);
        float bv0 = __ldg(&bias[r0]);
        float bv1 = __ldg(&bias[r0 + 8]);
        #pragma unroll
        for (int nt = 0; nt < 4; nt++) {
            int cidx = n0 + wn * 32 + nt * 8 + 2 * (lane & 3);
            float y0 = acc[mt][nt][0] + bv0;
            float y1 = acc[mt][nt][1] + bv0;
            float y2 = acc[mt][nt][2] + bv1;
            float y3 = acc[mt][nt][3] + bv1;
            y0 = (y0 >= 0.f ? y0 : 0.2f * y0) * S2;
            y1 = (y1 >= 0.f ? y1 : 0.2f * y1) * S2;
            y2 = (y2 >= 0.f ? y2 : 0.2f * y2) * S2;
            y3 = (y3 >= 0.f ? y3 : 0.2f * y3) * S2;
            if (OUT_M == 0) {
                *(float2*)(Yf + (size_t)r0 * NN + cidx)       = make_float2(y0, y1);
                *(float2*)(Yf + (size_t)(r0 + 8) * NN + cidx) = make_float2(y2, y3);
            } else {
                __nv_bfloat16 h0 = __float2bfloat16(y0);
                __nv_bfloat16 h1 = __float2bfloat16(y1);
                __nv_bfloat16 h2 = __float2bfloat16(y2);
                __nv_bfloat16 h3 = __float2bfloat16(y3);
                __nv_bfloat162 hp0; hp0.x = h0; hp0.y = h1;
                __nv_bfloat162 hp1; hp1.x = h2; hp1.y = h3;
                __nv_bfloat162 lp0;
                lp0.x = __float2bfloat16(y0 - __bfloat162float(h0));
                lp0.y = __float2bfloat16(y1 - __bfloat162float(h1));
                __nv_bfloat162 lp1;
                lp1.x = __float2bfloat16(y2 - __bfloat162float(h2));
                lp1.y = __float2bfloat16(y3 - __bfloat162float(h3));
                *(__nv_bfloat162*)(Yh + (size_t)r0 * NN + cidx)       = hp0;
                *(__nv_bfloat162*)(Yh + (size_t)(r0 + 8) * NN + cidx) = hp1;
                *(__nv_bfloat162*)(Yl + (size_t)r0 * NN + cidx)       = lp0;
                *(__nv_bfloat162*)(Yl + (size_t)(r0 + 8) * NN + cidx) = lp1;
            }
        }
    }
}

// ---------------------------------------------------------------------------
extern "C" void kernel_launch(void* const* d_in, const int* in_sizes, int n_in,
                              void* d_out, int out_size) {
    (void)in_sizes; (void)n_in; (void)out_size;
    const float* x = (const float*)d_in[0];
    const float* z = (const float*)d_in[1];
    ModArgs ma;
    const float* bb[3];
    for (int l = 0; l < 3; l++) {
        ma.w[l]  = (const float*)d_in[2 + 4 * l];
        ma.mw[l] = (const float*)d_in[3 + 4 * l];
        ma.mb[l] = (const float*)d_in[4 + 4 * l];
        bb[l]    = (const float*)d_in[5 + 4 * l];
    }
    float* out = (float*)d_out;

    cudaFuncSetAttribute(gemm_kernel<0, 1>, cudaFuncAttributeMaxDynamicSharedMemorySize, SMEM_BYTES);
    cudaFuncSetAttribute(gemm_kernel<1, 2>, cudaFuncAttributeMaxDynamicSharedMemorySize, SMEM_BYTES);
    cudaFuncSetAttribute(gemm_kernel<2, 0>, cudaFuncAttributeMaxDynamicSharedMemorySize, SMEM_BYTES);

    style_kernel<<<dim3(3, CB), 256>>>(z, ma);
    modw_kernel<<<dim3(3, CB), 256>>>(ma);

    dim3 grid(NN / BN, CC / BM, CB);
    gemm_kernel<0, 1><<<grid, 256, SMEM_BYTES>>>(x, bb[0], out, 0);
    gemm_kernel<1, 2><<<grid, 256, SMEM_BYTES>>>(x, bb[1], out, 1);
    gemm_kernel<2, 0><<<grid, 256, SMEM_BYTES>>>(x, bb[2], out, 2);
}

// round 6
// speedup vs baseline: 1.5061x; 1.5061x over previous
#include <cuda_runtime.h>
#include <cuda_bf16.h>
#include <cstdint>
#include <cstddef>

// ---------------------------------------------------------------------------
// StyledMLP: 3 chained modulated 1x1 convs (B=16, C=256, N=16384, S=512)
// Legacy mma.sync bf16 (tcgen05 rejected: harness emits compute_103 PTX).
// 3-term split-bf16 (hi*hi + hi*lo + lo*hi), fp32 accumulate.
// R5: exact R3 structure (2-stage pipeline, 75.8KB smem/CTA) + term-major
// MMA ordering ONLY (accumulator RAW reuse distance 1 -> 4).
// ---------------------------------------------------------------------------

#define CB   16
#define CC   256
#define NN   16384
#define SS   512

#define BM 128
#define BN 128
#define BK 32

// scratch (allocation-free rule: __device__ globals)
__device__ __nv_bfloat16 g_Xh0[(size_t)CB * CC * NN];
__device__ __nv_bfloat16 g_Xl0[(size_t)CB * CC * NN];
__device__ __nv_bfloat16 g_Xh1[(size_t)CB * CC * NN];
__device__ __nv_bfloat16 g_Xl1[(size_t)CB * CC * NN];
__device__ __nv_bfloat16 g_Whi[3 * CB * CC * CC];
__device__ __nv_bfloat16 g_Wlo[3 * CB * CC * CC];
__device__ float         g_style[3 * CB * CC];

// ---------------------------------------------------------------------------
// PTX helpers
// ---------------------------------------------------------------------------
__device__ __forceinline__ void cp16(void* sdst, const void* gsrc) {
    unsigned a = (unsigned)__cvta_generic_to_shared(sdst);
    asm volatile("cp.async.cg.shared.global [%0], [%1], 16;\n" :: "r"(a), "l"(gsrc));
}
__device__ __forceinline__ void cp_commit() {
    asm volatile("cp.async.commit_group;\n" ::: "memory");
}
__device__ __forceinline__ void ldsm4(uint32_t* r, const void* p) {
    unsigned a = (unsigned)__cvta_generic_to_shared(p);
    asm volatile("ldmatrix.sync.aligned.m8n8.x4.shared.b16 {%0,%1,%2,%3}, [%4];\n"
                 : "=r"(r[0]), "=r"(r[1]), "=r"(r[2]), "=r"(r[3]) : "r"(a));
}
__device__ __forceinline__ void ldsm4t(uint32_t* r, const void* p) {
    unsigned a = (unsigned)__cvta_generic_to_shared(p);
    asm volatile("ldmatrix.sync.aligned.m8n8.x4.trans.shared.b16 {%0,%1,%2,%3}, [%4];\n"
                 : "=r"(r[0]), "=r"(r[1]), "=r"(r[2]), "=r"(r[3]) : "r"(a));
}
// pack(lo_elem, hi_elem): low 16 bits = first (smaller k) element
__device__ __forceinline__ uint32_t packbf(float lo, float hi) {
    uint32_t r;
    asm("cvt.rn.bf16x2.f32 %0, %1, %2;" : "=r"(r) : "f"(hi), "f"(lo));
    return r;
}
__device__ __forceinline__ void mma16816(float* c, const uint32_t* a, uint32_t b0, uint32_t b1) {
    asm volatile("mma.sync.aligned.m16n8k16.row.col.f32.bf16.bf16.f32 "
                 "{%0,%1,%2,%3}, {%4,%5,%6,%7}, {%8,%9}, {%0,%1,%2,%3};\n"
                 : "+f"(c[0]), "+f"(c[1]), "+f"(c[2]), "+f"(c[3])
                 : "r"(a[0]), "r"(a[1]), "r"(a[2]), "r"(a[3]), "r"(b0), "r"(b1));
}
__device__ __forceinline__ float warp_sum(float v) {
    #pragma unroll
    for (int o = 16; o; o >>= 1) v += __shfl_xor_sync(0xffffffffu, v, o);
    return v;
}

// ---------------------------------------------------------------------------
// Modulation stage 1: style[l][b][c] = (z[b] . mw[l][c]) / sqrt(512) + mb[l][c]
// ---------------------------------------------------------------------------
struct ModArgs {
    const float* w[3];
    const float* mw[3];
    const float* mb[3];
};

__global__ void style_kernel(const float* __restrict__ z, ModArgs args) {
    int layer = blockIdx.x, b = blockIdx.y;
    int tid = threadIdx.x, warp = tid >> 5, lane = tid & 31;
    __shared__ float zs[SS];
    for (int i = tid; i < SS; i += 256) zs[i] = z[(size_t)b * SS + i];
    __syncthreads();

    const float* mw = args.mw[layer];
    const float* mb = args.mb[layer];
    for (int c = warp; c < CC; c += 8) {
        const float* row = mw + (size_t)c * SS;
        float s = 0.f;
        #pragma unroll
        for (int j = 0; j < SS / 32; j++)
            s = fmaf(row[lane + 32 * j], zs[lane + 32 * j], s);
        s = warp_sum(s);
        if (lane == 0)
            g_style[((size_t)layer * CB + b) * CC + c] =
                s * 0.04419417382415922f + mb[c];
    }
}

// ---------------------------------------------------------------------------
// Modulation stage 2: demodulate + split W into bf16 hi/lo. Warp-per-row.
// ---------------------------------------------------------------------------
__global__ void modw_kernel(ModArgs args) {
    int layer = blockIdx.x, b = blockIdx.y;
    int tid = threadIdx.x, warp = tid >> 5, lane = tid & 31;
    __shared__ float st[CC];
    for (int i = tid; i < CC; i += 256)
        st[i] = g_style[((size_t)layer * CB + b) * CC + i];
    __syncthreads();

    const float* w = args.w[layer];
    __nv_bfloat16* oh = g_Whi + ((size_t)(layer * CB + b)) * CC * CC;
    __nv_bfloat16* ol = g_Wlo + ((size_t)(layer * CB + b)) * CC * CC;

    for (int r = warp; r < CC; r += 8) {
        const float* wr = w + (size_t)r * CC;
        float s2 = 0.f;
        #pragma unroll
        for (int j = 0; j < CC / 32; j++) {
            float v = wr[lane + 32 * j] * st[lane + 32 * j];
            s2 = fmaf(v, v, s2);
        }
        s2 = warp_sum(s2);
        float ss = s2 * (0.0625f * 0.0625f) + 1e-8f;
        float d = rsqrtf(ss);
        d = d * (1.5f - 0.5f * ss * d * d);          // Newton refine
        float scale = 0.0625f * d;
        #pragma unroll
        for (int j = 0; j < CC / 32; j++) {
            int i = lane + 32 * j;
            float v = wr[i] * st[i] * scale;
            __nv_bfloat16 h = __float2bfloat16(v);
            oh[(size_t)r * CC + i] = h;
            ol[(size_t)r * CC + i] = __float2bfloat16(v - __bfloat162float(h));
        }
    }
}

// ---------------------------------------------------------------------------
// GEMM smem layout (per stage, bytes), 2 stages:
//   [0,10240)       W hi : 128 rows x 40 bf16 (32 used + pad)
//   [10240,20480)   W lo
//   [20480,37888)   X region:
//       fp32 path:  staging 32 rows x 132 f32 (pitch 528B) = 16896
//       bf16 path:  Xhi 32x136 bf16 (pitch 272B) = 8704, Xlo at +8704
// ---------------------------------------------------------------------------
#define WPITCH 40
#define STG_PITCHF 132
#define XP 136
#define XPLANE 8704
#define PS 37888
#define SMEM_BYTES (2 * PS)

template<int IN_M>  // 0 = fp32 harness x, 1 = bf16 planes g_Xh0/g_Xl0, 2 = g_Xh1/g_Xl1
__device__ __forceinline__ void load_stage(char* sm, int stage,
                                           const __nv_bfloat16* gWh,
                                           const __nv_bfloat16* gWl,
                                           const float* Xf,
                                           const __nv_bfloat16* Xh,
                                           const __nv_bfloat16* Xl,
                                           int k0, int n0, int tid) {
    char* base = sm + stage * PS;
    #pragma unroll
    for (int i = 0; i < 2; i++) {                 // W hi+lo: 128x32 bf16
        int c = tid + i * 256;                    // 0..511
        int row = c >> 2, cc = c & 3;
        cp16(base + (row * WPITCH + cc * 8) * 2, gWh + (size_t)row * CC + k0 + cc * 8);
        cp16(base + 10240 + (row * WPITCH + cc * 8) * 2, gWl + (size_t)row * CC + k0 + cc * 8);
    }
    if (IN_M == 0) {
        #pragma unroll
        for (int i = 0; i < 4; i++) {             // X fp32: 32x128
            int c = tid + i * 256;                // 0..1023
            int row = c >> 5, cc = c & 31;
            cp16(base + 20480 + row * (STG_PITCHF * 4) + cc * 16,
                 Xf + (size_t)(k0 + row) * NN + n0 + cc * 4);
        }
    } else {
        #pragma unroll
        for (int i = 0; i < 4; i++) {             // X bf16 hi+lo: 32x128 each
            int c = tid + i * 256;                // 0..1023
            int plane = c >> 9;                   // 0=hi,1=lo
            int cc5 = c & 511;
            int row = cc5 >> 4, cc = cc5 & 15;
            const __nv_bfloat16* src = (plane ? Xl : Xh) + (size_t)(k0 + row) * NN + n0 + cc * 8;
            cp16(base + 20480 + plane * XPLANE + (row * XP + cc * 8) * 2, src);
        }
    }
}

// ---------------------------------------------------------------------------
// Fused modulated-conv GEMM. CTA 128x128, 8 warps (warp tile 64x32), K=256.
// 2-stage pipeline, term-major MMA ordering (acc reuse distance 4).
// ---------------------------------------------------------------------------
template<int IN_M, int OUT_M>
__global__ void __launch_bounds__(256, 2)
gemm_kernel(const float* __restrict__ xin, const float* __restrict__ bias,
            float* __restrict__ yout, int layer) {
    extern __shared__ __align__(128) char sm[];

    const __nv_bfloat16* Xh_in = (IN_M == 1) ? g_Xh0 : g_Xh1;
    const __nv_bfloat16* Xl_in = (IN_M == 1) ? g_Xl0 : g_Xl1;

    int b  = blockIdx.z;
    int m0 = blockIdx.y * BM;
    int n0 = blockIdx.x * BN;
    int tid  = threadIdx.x;
    int lane = tid & 31;
    int warp = tid >> 5;
    int wm = warp & 1;      // 2 warps along M
    int wn = warp >> 1;     // 4 warps along N

    const __nv_bfloat16* gWh = g_Whi + ((size_t)(layer * CB + b)) * CC * CC + (size_t)m0 * CC;
    const __nv_bfloat16* gWl = g_Wlo + ((size_t)(layer * CB + b)) * CC * CC + (size_t)m0 * CC;
    const float* Xf = (IN_M == 0) ? (xin + (size_t)b * CC * NN) : nullptr;
    const __nv_bfloat16* Xh = (IN_M == 0) ? nullptr : Xh_in + (size_t)b * CC * NN;
    const __nv_bfloat16* Xl = (IN_M == 0) ? nullptr : Xl_in + (size_t)b * CC * NN;

    float acc[4][4][4];
    #pragma unroll
    for (int i = 0; i < 4; i++)
        #pragma unroll
        for (int j = 0; j < 4; j++)
            #pragma unroll
            for (int k = 0; k < 4; k++) acc[i][j][k] = 0.f;

    load_stage<IN_M>(sm, 0, gWh, gWl, Xf, Xh, Xl, 0, n0, tid);
    cp_commit();

    #pragma unroll 1
    for (int ch = 0; ch < 8; ch++) {
        int stage = ch & 1;
        if (ch < 7) {
            load_stage<IN_M>(sm, stage ^ 1, gWh, gWl, Xf, Xh, Xl, (ch + 1) * BK, n0, tid);
            cp_commit();
            asm volatile("cp.async.wait_group 1;\n" ::: "memory");
        } else {
            asm volatile("cp.async.wait_group 0;\n" ::: "memory");
        }
        __syncthreads();

        char* base = sm + stage * PS;
        const __nv_bfloat16* Whi = (const __nv_bfloat16*)base;
        const __nv_bfloat16* Wlo = (const __nv_bfloat16*)(base + 10240);

        #pragma unroll
        for (int kk = 0; kk < BK; kk += 16) {
            uint32_t ah[4][4], al[4][4];
            #pragma unroll
            for (int mt = 0; mt < 4; mt++) {
                int row = wm * 64 + mt * 16 + (lane & 15);
                int col = kk + ((lane >> 4) << 3);
                ldsm4(ah[mt], &Whi[row * WPITCH + col]);
                ldsm4(al[mt], &Wlo[row * WPITCH + col]);
            }
            if (IN_M == 0) {
                const float* Xst = (const float*)(base + 20480);
                #pragma unroll
                for (int nt = 0; nt < 4; nt++) {
                    int n  = wn * 32 + nt * 8 + (lane >> 2);
                    int kb = kk + 2 * (lane & 3);
                    const float* xp = Xst + kb * STG_PITCHF + n;
                    float x0 = xp[0];
                    float x1 = xp[STG_PITCHF];
                    float x2 = xp[8 * STG_PITCHF];
                    float x3 = xp[9 * STG_PITCHF];
                    uint32_t bh0 = packbf(x0, x1);
                    uint32_t bh1 = packbf(x2, x3);
                    float h0 = __uint_as_float(bh0 << 16);
                    float h1 = __uint_as_float(bh0 & 0xffff0000u);
                    float h2 = __uint_as_float(bh1 << 16);
                    float h3 = __uint_as_float(bh1 & 0xffff0000u);
                    uint32_t bl0 = packbf(x0 - h0, x1 - h1);
                    uint32_t bl1 = packbf(x2 - h2, x3 - h3);
                    // term-major within nt: same-acc reuse distance 4
                    #pragma unroll
                    for (int mt = 0; mt < 4; mt++) mma16816(acc[mt][nt], ah[mt], bh0, bh1);
                    #pragma unroll
                    for (int mt = 0; mt < 4; mt++) mma16816(acc[mt][nt], ah[mt], bl0, bl1);
                    #pragma unroll
                    for (int mt = 0; mt < 4; mt++) mma16816(acc[mt][nt], al[mt], bh0, bh1);
                }
            } else {
                const __nv_bfloat16* sXh = (const __nv_bfloat16*)(base + 20480);
                const __nv_bfloat16* sXl = (const __nv_bfloat16*)(base + 20480 + XPLANE);
                uint32_t bh[2][4], bl[2][4];
                #pragma unroll
                for (int c2 = 0; c2 < 2; c2++) {
                    int k = kk + ((lane >> 3) & 1) * 8 + (lane & 7);
                    int n = wn * 32 + c2 * 16 + (lane >> 4) * 8;
                    ldsm4t(bh[c2], &sXh[k * XP + n]);
                    ldsm4t(bl[c2], &sXl[k * XP + n]);
                }
                // term-major within nt: same-acc reuse distance 4
                #pragma unroll
                for (int nt = 0; nt < 4; nt++) {
                    int c2 = nt >> 1, sub = (nt & 1) * 2;
                    uint32_t b0h = bh[c2][sub], b1h = bh[c2][sub + 1];
                    uint32_t b0l = bl[c2][sub], b1l = bl[c2][sub + 1];
                    #pragma unroll
                    for (int mt = 0; mt < 4; mt++) mma16816(acc[mt][nt], ah[mt], b0h, b1h);
                    #pragma unroll
                    for (int mt = 0; mt < 4; mt++) mma16816(acc[mt][nt], ah[mt], b0l, b1l);
                    #pragma unroll
                    for (int mt = 0; mt < 4; mt++) mma16816(acc[mt][nt], al[mt], b0h, b1h);
                }
            }
        }
        __syncthreads();
    }

    // epilogue: bias + leaky(0.2) * sqrt(2); write fp32 or bf16 hi/lo planes
    const float S2 = 1.4142135623730951f;
    __nv_bfloat16* Yh = (OUT_M == 1) ? g_Xh0 : g_Xh1;
    __nv_bfloat16* Yl = (OUT_M == 1) ? g_Xl0 : g_Xl1;
    float* Yf = (OUT_M == 0) ? (yout + (size_t)b * CC * NN) : nullptr;
    if (OUT_M != 0) { Yh += (size_t)b * CC * NN; Yl += (size_t)b * CC * NN; }

    #pragma unroll
    for (int mt = 0; mt < 4; mt++) {
        int r0 = m0 + wm * 64 + mt * 16 + (lane >> 2);
        float bv0 = __ldg(&bias[r0]);
        float bv1 = __ldg(&bias[r0 + 8]);
        #pragma unroll
        for (int nt = 0; nt < 4; nt++) {
            int cidx = n0 + wn * 32 + nt * 8 + 2 * (lane & 3);
            float y0 = acc[mt][nt][0] + bv0;
            float y1 = acc[mt][nt][1] + bv0;
            float y2 = acc[mt][nt][2] + bv1;
            float y3 = acc[mt][nt][3] + bv1;
            y0 = (y0 >= 0.f ? y0 : 0.2f * y0) * S2;
            y1 = (y1 >= 0.f ? y1 : 0.2f * y1) * S2;
            y2 = (y2 >= 0.f ? y2 : 0.2f * y2) * S2;
            y3 = (y3 >= 0.f ? y3 : 0.2f * y3) * S2;
            if (OUT_M == 0) {
                *(float2*)(Yf + (size_t)r0 * NN + cidx)       = make_float2(y0, y1);
                *(float2*)(Yf + (size_t)(r0 + 8) * NN + cidx) = make_float2(y2, y3);
            } else {
                __nv_bfloat16 h0 = __float2bfloat16(y0);
                __nv_bfloat16 h1 = __float2bfloat16(y1);
                __nv_bfloat16 h2 = __float2bfloat16(y2);
                __nv_bfloat16 h3 = __float2bfloat16(y3);
                __nv_bfloat162 hp0; hp0.x = h0; hp0.y = h1;
                __nv_bfloat162 hp1; hp1.x = h2; hp1.y = h3;
                __nv_bfloat162 lp0;
                lp0.x = __float2bfloat16(y0 - __bfloat162float(h0));
                lp0.y = __float2bfloat16(y1 - __bfloat162float(h1));
                __nv_bfloat162 lp1;
                lp1.x = __float2bfloat16(y2 - __bfloat162float(h2));
                lp1.y = __float2bfloat16(y3 - __bfloat162float(h3));
                *(__nv_bfloat162*)(Yh + (size_t)r0 * NN + cidx)       = hp0;
                *(__nv_bfloat162*)(Yh + (size_t)(r0 + 8) * NN + cidx) = hp1;
                *(__nv_bfloat162*)(Yl + (size_t)r0 * NN + cidx)       = lp0;
                *(__nv_bfloat162*)(Yl + (size_t)(r0 + 8) * NN + cidx) = lp1;
            }
        }
    }
}

// ---------------------------------------------------------------------------
extern "C" void kernel_launch(void* const* d_in, const int* in_sizes, int n_in,
                              void* d_out, int out_size) {
    (void)in_sizes; (void)n_in; (void)out_size;
    const float* x = (const float*)d_in[0];
    const float* z = (const float*)d_in[1];
    ModArgs ma;
    const float* bb[3];
    for (int l = 0; l < 3; l++) {
        ma.w[l]  = (const float*)d_in[2 + 4 * l];
        ma.mw[l] = (const float*)d_in[3 + 4 * l];
        ma.mb[l] = (const float*)d_in[4 + 4 * l];
        bb[l]    = (const float*)d_in[5 + 4 * l];
    }
    float* out = (float*)d_out;

    cudaFuncSetAttribute(gemm_kernel<0, 1>, cudaFuncAttributeMaxDynamicSharedMemorySize, SMEM_BYTES);
    cudaFuncSetAttribute(gemm_kernel<1, 2>, cudaFuncAttributeMaxDynamicSharedMemorySize, SMEM_BYTES);
    cudaFuncSetAttribute(gemm_kernel<2, 0>, cudaFuncAttributeMaxDynamicSharedMemorySize, SMEM_BYTES);

    style_kernel<<<dim3(3, CB), 256>>>(z, ma);
    modw_kernel<<<dim3(3, CB), 256>>>(ma);

    dim3 grid(NN / BN, CC / BM, CB);
    gemm_kernel<0, 1><<<grid, 256, SMEM_BYTES>>>(x, bb[0], out, 0);
    gemm_kernel<1, 2><<<grid, 256, SMEM_BYTES>>>(x, bb[1], out, 1);
    gemm_kernel<2, 0><<<grid, 256, SMEM_BYTES>>>(x, bb[2], out, 2);
}

// round 7
// speedup vs baseline: 1.5805x; 1.0494x over previous
#include <cuda_runtime.h>
#include <cuda_bf16.h>
#include <cstdint>
#include <cstddef>

// ---------------------------------------------------------------------------
// StyledMLP: 3 chained modulated 1x1 convs (B=16, C=256, N=16384, S=512)
// Legacy mma.sync bf16 (tcgen05 rejected: harness emits compute_103 PTX).
// 3-term split-bf16 (hi*hi + hi*lo + lo*hi), fp32 accumulate.
// R6: warp tile 64x64, 4 warps/CTA (128 thr), single barrier per chunk.
// ---------------------------------------------------------------------------

#define CB   16
#define CC   256
#define NN   16384
#define SS   512

#define BM 128
#define BN 128
#define BK 32
#define NT 128          // threads per CTA

// scratch (allocation-free rule: __device__ globals)
__device__ __nv_bfloat16 g_Xh0[(size_t)CB * CC * NN];
__device__ __nv_bfloat16 g_Xl0[(size_t)CB * CC * NN];
__device__ __nv_bfloat16 g_Xh1[(size_t)CB * CC * NN];
__device__ __nv_bfloat16 g_Xl1[(size_t)CB * CC * NN];
__device__ __nv_bfloat16 g_Whi[3 * CB * CC * CC];
__device__ __nv_bfloat16 g_Wlo[3 * CB * CC * CC];
__device__ float         g_style[3 * CB * CC];

// ---------------------------------------------------------------------------
// PTX helpers
// ---------------------------------------------------------------------------
__device__ __forceinline__ void cp16(void* sdst, const void* gsrc) {
    unsigned a = (unsigned)__cvta_generic_to_shared(sdst);
    asm volatile("cp.async.cg.shared.global [%0], [%1], 16;\n" :: "r"(a), "l"(gsrc));
}
__device__ __forceinline__ void cp_commit() {
    asm volatile("cp.async.commit_group;\n" ::: "memory");
}
__device__ __forceinline__ void ldsm4(uint32_t* r, const void* p) {
    unsigned a = (unsigned)__cvta_generic_to_shared(p);
    asm volatile("ldmatrix.sync.aligned.m8n8.x4.shared.b16 {%0,%1,%2,%3}, [%4];\n"
                 : "=r"(r[0]), "=r"(r[1]), "=r"(r[2]), "=r"(r[3]) : "r"(a));
}
__device__ __forceinline__ void ldsm4t(uint32_t* r, const void* p) {
    unsigned a = (unsigned)__cvta_generic_to_shared(p);
    asm volatile("ldmatrix.sync.aligned.m8n8.x4.trans.shared.b16 {%0,%1,%2,%3}, [%4];\n"
                 : "=r"(r[0]), "=r"(r[1]), "=r"(r[2]), "=r"(r[3]) : "r"(a));
}
// pack(lo_elem, hi_elem): low 16 bits = first (smaller k) element
__device__ __forceinline__ uint32_t packbf(float lo, float hi) {
    uint32_t r;
    asm("cvt.rn.bf16x2.f32 %0, %1, %2;" : "=r"(r) : "f"(hi), "f"(lo));
    return r;
}
__device__ __forceinline__ void mma16816(float* c, const uint32_t* a, uint32_t b0, uint32_t b1) {
    asm volatile("mma.sync.aligned.m16n8k16.row.col.f32.bf16.bf16.f32 "
                 "{%0,%1,%2,%3}, {%4,%5,%6,%7}, {%8,%9}, {%0,%1,%2,%3};\n"
                 : "+f"(c[0]), "+f"(c[1]), "+f"(c[2]), "+f"(c[3])
                 : "r"(a[0]), "r"(a[1]), "r"(a[2]), "r"(a[3]), "r"(b0), "r"(b1));
}
__device__ __forceinline__ float warp_sum(float v) {
    #pragma unroll
    for (int o = 16; o; o >>= 1) v += __shfl_xor_sync(0xffffffffu, v, o);
    return v;
}

// ---------------------------------------------------------------------------
// Modulation (unchanged from R3/R5 — measured fast)
// ---------------------------------------------------------------------------
struct ModArgs {
    const float* w[3];
    const float* mw[3];
    const float* mb[3];
};

__global__ void style_kernel(const float* __restrict__ z, ModArgs args) {
    int layer = blockIdx.x, b = blockIdx.y;
    int tid = threadIdx.x, warp = tid >> 5, lane = tid & 31;
    __shared__ float zs[SS];
    for (int i = tid; i < SS; i += 256) zs[i] = z[(size_t)b * SS + i];
    __syncthreads();

    const float* mw = args.mw[layer];
    const float* mb = args.mb[layer];
    for (int c = warp; c < CC; c += 8) {
        const float* row = mw + (size_t)c * SS;
        float s = 0.f;
        #pragma unroll
        for (int j = 0; j < SS / 32; j++)
            s = fmaf(row[lane + 32 * j], zs[lane + 32 * j], s);
        s = warp_sum(s);
        if (lane == 0)
            g_style[((size_t)layer * CB + b) * CC + c] =
                s * 0.04419417382415922f + mb[c];
    }
}

__global__ void modw_kernel(ModArgs args) {
    int layer = blockIdx.x, b = blockIdx.y;
    int tid = threadIdx.x, warp = tid >> 5, lane = tid & 31;
    __shared__ float st[CC];
    for (int i = tid; i < CC; i += 256)
        st[i] = g_style[((size_t)layer * CB + b) * CC + i];
    __syncthreads();

    const float* w = args.w[layer];
    __nv_bfloat16* oh = g_Whi + ((size_t)(layer * CB + b)) * CC * CC;
    __nv_bfloat16* ol = g_Wlo + ((size_t)(layer * CB + b)) * CC * CC;

    for (int r = warp; r < CC; r += 8) {
        const float* wr = w + (size_t)r * CC;
        float s2 = 0.f;
        #pragma unroll
        for (int j = 0; j < CC / 32; j++) {
            float v = wr[lane + 32 * j] * st[lane + 32 * j];
            s2 = fmaf(v, v, s2);
        }
        s2 = warp_sum(s2);
        float ss = s2 * (0.0625f * 0.0625f) + 1e-8f;
        float d = rsqrtf(ss);
        d = d * (1.5f - 0.5f * ss * d * d);
        float scale = 0.0625f * d;
        #pragma unroll
        for (int j = 0; j < CC / 32; j++) {
            int i = lane + 32 * j;
            float v = wr[i] * st[i] * scale;
            __nv_bfloat16 h = __float2bfloat16(v);
            oh[(size_t)r * CC + i] = h;
            ol[(size_t)r * CC + i] = __float2bfloat16(v - __bfloat162float(h));
        }
    }
}

// ---------------------------------------------------------------------------
// GEMM smem layout (per stage, bytes), 2 stages (unchanged from R3):
//   [0,10240)       W hi : 128 rows x 40 bf16 (32 used + pad)
//   [10240,20480)   W lo
//   [20480,37888)   X region:
//       fp32 path:  staging 32 rows x 132 f32 (pitch 528B) = 16896
//       bf16 path:  Xhi 32x136 bf16 (pitch 272B) = 8704, Xlo at +8704
// ---------------------------------------------------------------------------
#define WPITCH 40
#define STG_PITCHF 132
#define XP 136
#define XPLANE 8704
#define PS 37888
#define SMEM_BYTES (2 * PS)

template<int IN_M>  // 0 = fp32 harness x, 1 = planes g_Xh0/g_Xl0, 2 = g_Xh1/g_Xl1
__device__ __forceinline__ void load_stage(char* sm, int stage,
                                           const __nv_bfloat16* gWh,
                                           const __nv_bfloat16* gWl,
                                           const float* Xf,
                                           const __nv_bfloat16* Xh,
                                           const __nv_bfloat16* Xl,
                                           int k0, int n0, int tid) {
    char* base = sm + stage * PS;
    #pragma unroll
    for (int i = 0; i < 4; i++) {                 // W hi+lo: 128x32 bf16 each
        int c = tid + i * NT;                     // 0..511
        int row = c >> 2, cc = c & 3;
        cp16(base + (row * WPITCH + cc * 8) * 2, gWh + (size_t)row * CC + k0 + cc * 8);
        cp16(base + 10240 + (row * WPITCH + cc * 8) * 2, gWl + (size_t)row * CC + k0 + cc * 8);
    }
    if (IN_M == 0) {
        #pragma unroll
        for (int i = 0; i < 8; i++) {             // X fp32: 32x128
            int c = tid + i * NT;                 // 0..1023
            int row = c >> 5, cc = c & 31;
            cp16(base + 20480 + row * (STG_PITCHF * 4) + cc * 16,
                 Xf + (size_t)(k0 + row) * NN + n0 + cc * 4);
        }
    } else {
        #pragma unroll
        for (int i = 0; i < 4; i++) {             // X hi: 32x128 bf16
            int c = tid + i * NT;                 // 0..511
            int row = c >> 4, cc = c & 15;
            cp16(base + 20480 + (row * XP + cc * 8) * 2,
                 Xh + (size_t)(k0 + row) * NN + n0 + cc * 8);
        }
        #pragma unroll
        for (int i = 0; i < 4; i++) {             // X lo: 32x128 bf16
            int c = tid + i * NT;
            int row = c >> 4, cc = c & 15;
            cp16(base + 20480 + XPLANE + (row * XP + cc * 8) * 2,
                 Xl + (size_t)(k0 + row) * NN + n0 + cc * 8);
        }
    }
}

// ---------------------------------------------------------------------------
// GEMM. CTA 128x128, 4 warps (warp tile 64x64, grid 2x2), K=256,
// 2-stage pipeline, ONE barrier per chunk.
// ---------------------------------------------------------------------------
template<int IN_M, int OUT_M>
__global__ void __launch_bounds__(NT, 2)
gemm_kernel(const float* __restrict__ xin, const float* __restrict__ bias,
            float* __restrict__ yout, int layer) {
    extern __shared__ __align__(128) char sm[];

    const __nv_bfloat16* Xh_in = (IN_M == 1) ? g_Xh0 : g_Xh1;
    const __nv_bfloat16* Xl_in = (IN_M == 1) ? g_Xl0 : g_Xl1;

    int b  = blockIdx.z;
    int m0 = blockIdx.y * BM;
    int n0 = blockIdx.x * BN;
    int tid  = threadIdx.x;
    int lane = tid & 31;
    int warp = tid >> 5;
    int wm = warp & 1;      // 2 warps along M (64 rows each)
    int wn = warp >> 1;     // 2 warps along N (64 cols each)

    const __nv_bfloat16* gWh = g_Whi + ((size_t)(layer * CB + b)) * CC * CC + (size_t)m0 * CC;
    const __nv_bfloat16* gWl = g_Wlo + ((size_t)(layer * CB + b)) * CC * CC + (size_t)m0 * CC;
    const float* Xf = (IN_M == 0) ? (xin + (size_t)b * CC * NN) : nullptr;
    const __nv_bfloat16* Xh = (IN_M == 0) ? nullptr : Xh_in + (size_t)b * CC * NN;
    const __nv_bfloat16* Xl = (IN_M == 0) ? nullptr : Xl_in + (size_t)b * CC * NN;

    float acc[4][8][4];
    #pragma unroll
    for (int i = 0; i < 4; i++)
        #pragma unroll
        for (int j = 0; j < 8; j++)
            #pragma unroll
            for (int k = 0; k < 4; k++) acc[i][j][k] = 0.f;

    load_stage<IN_M>(sm, 0, gWh, gWl, Xf, Xh, Xl, 0, n0, tid);
    cp_commit();

    #pragma unroll 1
    for (int ch = 0; ch < 8; ch++) {
        int stage = ch & 1;
        asm volatile("cp.async.wait_group 0;\n" ::: "memory");
        __syncthreads();   // stage data visible; stage^1 readers (chunk ch-1) done

        if (ch < 7) {
            load_stage<IN_M>(sm, stage ^ 1, gWh, gWl, Xf, Xh, Xl, (ch + 1) * BK, n0, tid);
            cp_commit();
        }

        char* base = sm + stage * PS;
        const __nv_bfloat16* Whi = (const __nv_bfloat16*)base;
        const __nv_bfloat16* Wlo = (const __nv_bfloat16*)(base + 10240);

        #pragma unroll
        for (int kk = 0; kk < BK; kk += 16) {
            uint32_t ah[4][4], al[4][4];
            #pragma unroll
            for (int mt = 0; mt < 4; mt++) {
                int row = wm * 64 + mt * 16 + (lane & 15);
                int col = kk + ((lane >> 4) << 3);
                ldsm4(ah[mt], &Whi[row * WPITCH + col]);
                ldsm4(al[mt], &Wlo[row * WPITCH + col]);
            }
            if (IN_M == 0) {
                const float* Xst = (const float*)(base + 20480);
                #pragma unroll
                for (int nt = 0; nt < 8; nt++) {
                    int n  = wn * 64 + nt * 8 + (lane >> 2);
                    int kb = kk + 2 * (lane & 3);
                    const float* xp = Xst + kb * STG_PITCHF + n;
                    float x0 = xp[0];
                    float x1 = xp[STG_PITCHF];
                    float x2 = xp[8 * STG_PITCHF];
                    float x3 = xp[9 * STG_PITCHF];
                    uint32_t bh0 = packbf(x0, x1);
                    uint32_t bh1 = packbf(x2, x3);
                    float h0 = __uint_as_float(bh0 << 16);
                    float h1 = __uint_as_float(bh0 & 0xffff0000u);
                    float h2 = __uint_as_float(bh1 << 16);
                    float h3 = __uint_as_float(bh1 & 0xffff0000u);
                    uint32_t bl0 = packbf(x0 - h0, x1 - h1);
                    uint32_t bl1 = packbf(x2 - h2, x3 - h3);
                    #pragma unroll
                    for (int mt = 0; mt < 4; mt++) mma16816(acc[mt][nt], ah[mt], bh0, bh1);
                    #pragma unroll
                    for (int mt = 0; mt < 4; mt++) mma16816(acc[mt][nt], ah[mt], bl0, bl1);
                    #pragma unroll
                    for (int mt = 0; mt < 4; mt++) mma16816(acc[mt][nt], al[mt], bh0, bh1);
                }
            } else {
                const __nv_bfloat16* sXh = (const __nv_bfloat16*)(base + 20480);
                const __nv_bfloat16* sXl = (const __nv_bfloat16*)(base + 20480 + XPLANE);
                uint32_t bh[4][4], bl[4][4];
                #pragma unroll
                for (int c2 = 0; c2 < 4; c2++) {
                    int k = kk + ((lane >> 3) & 1) * 8 + (lane & 7);
                    int n = wn * 64 + c2 * 16 + (lane >> 4) * 8;
                    ldsm4t(bh[c2], &sXh[k * XP + n]);
                    ldsm4t(bl[c2], &sXl[k * XP + n]);
                }
                // term-major: 32 independent MMAs per term
                #pragma unroll
                for (int nt = 0; nt < 8; nt++) {
                    int c2 = nt >> 1, sub = (nt & 1) * 2;
                    #pragma unroll
                    for (int mt = 0; mt < 4; mt++)
                        mma16816(acc[mt][nt], ah[mt], bh[c2][sub], bh[c2][sub + 1]);
                }
                #pragma unroll
                for (int nt = 0; nt < 8; nt++) {
                    int c2 = nt >> 1, sub = (nt & 1) * 2;
                    #pragma unroll
                    for (int mt = 0; mt < 4; mt++)
                        mma16816(acc[mt][nt], ah[mt], bl[c2][sub], bl[c2][sub + 1]);
                }
                #pragma unroll
                for (int nt = 0; nt < 8; nt++) {
                    int c2 = nt >> 1, sub = (nt & 1) * 2;
                    #pragma unroll
                    for (int mt = 0; mt < 4; mt++)
                        mma16816(acc[mt][nt], al[mt], bh[c2][sub], bh[c2][sub + 1]);
                }
            }
        }
    }

    // epilogue: bias + leaky(0.2) * sqrt(2); write fp32 or bf16 hi/lo planes
    const float S2 = 1.4142135623730951f;
    __nv_bfloat16* Yh = (OUT_M == 1) ? g_Xh0 : g_Xh1;
    __nv_bfloat16* Yl = (OUT_M == 1) ? g_Xl0 : g_Xl1;
    float* Yf = (OUT_M == 0) ? (yout + (size_t)b * CC * NN) : nullptr;
    if (OUT_M != 0) { Yh += (size_t)b * CC * NN; Yl += (size_t)b * CC * NN; }

    #pragma unroll
    for (int mt = 0; mt < 4; mt++) {
        int r0 = m0 + wm * 64 + mt * 16 + (lane >> 2);
        float bv0 = __ldg(&bias[r0]);
        float bv1 = __ldg(&bias[r0 + 8]);
        #pragma unroll
        for (int nt = 0; nt < 8; nt++) {
            int cidx = n0 + wn * 64 + nt * 8 + 2 * (lane & 3);
            float y0 = acc[mt][nt][0] + bv0;
            float y1 = acc[mt][nt][1] + bv0;
            float y2 = acc[mt][nt][2] + bv1;
            float y3 = acc[mt][nt][3] + bv1;
            y0 = (y0 >= 0.f ? y0 : 0.2f * y0) * S2;
            y1 = (y1 >= 0.f ? y1 : 0.2f * y1) * S2;
            y2 = (y2 >= 0.f ? y2 : 0.2f * y2) * S2;
            y3 = (y3 >= 0.f ? y3 : 0.2f * y3) * S2;
            if (OUT_M == 0) {
                *(float2*)(Yf + (size_t)r0 * NN + cidx)       = make_float2(y0, y1);
                *(float2*)(Yf + (size_t)(r0 + 8) * NN + cidx) = make_float2(y2, y3);
            } else {
                __nv_bfloat16 h0 = __float2bfloat16(y0);
                __nv_bfloat16 h1 = __float2bfloat16(y1);
                __nv_bfloat16 h2 = __float2bfloat16(y2);
                __nv_bfloat16 h3 = __float2bfloat16(y3);
                __nv_bfloat162 hp0; hp0.x = h0; hp0.y = h1;
                __nv_bfloat162 hp1; hp1.x = h2; hp1.y = h3;
                __nv_bfloat162 lp0;
                lp0.x = __float2bfloat16(y0 - __bfloat162float(h0));
                lp0.y = __float2bfloat16(y1 - __bfloat162float(h1));
                __nv_bfloat162 lp1;
                lp1.x = __float2bfloat16(y2 - __bfloat162float(h2));
                lp1.y = __float2bfloat16(y3 - __bfloat162float(h3));
                *(__nv_bfloat162*)(Yh + (size_t)r0 * NN + cidx)       = hp0;
                *(__nv_bfloat162*)(Yh + (size_t)(r0 + 8) * NN + cidx) = hp1;
                *(__nv_bfloat162*)(Yl + (size_t)r0 * NN + cidx)       = lp0;
                *(__nv_bfloat162*)(Yl + (size_t)(r0 + 8) * NN + cidx) = lp1;
            }
        }
    }
}

// ---------------------------------------------------------------------------
extern "C" void kernel_launch(void* const* d_in, const int* in_sizes, int n_in,
                              void* d_out, int out_size) {
    (void)in_sizes; (void)n_in; (void)out_size;
    const float* x = (const float*)d_in[0];
    const float* z = (const float*)d_in[1];
    ModArgs ma;
    const float* bb[3];
    for (int l = 0; l < 3; l++) {
        ma.w[l]  = (const float*)d_in[2 + 4 * l];
        ma.mw[l] = (const float*)d_in[3 + 4 * l];
        ma.mb[l] = (const float*)d_in[4 + 4 * l];
        bb[l]    = (const float*)d_in[5 + 4 * l];
    }
    float* out = (float*)d_out;

    cudaFuncSetAttribute(gemm_kernel<0, 1>, cudaFuncAttributeMaxDynamicSharedMemorySize, SMEM_BYTES);
    cudaFuncSetAttribute(gemm_kernel<1, 2>, cudaFuncAttributeMaxDynamicSharedMemorySize, SMEM_BYTES);
    cudaFuncSetAttribute(gemm_kernel<2, 0>, cudaFuncAttributeMaxDynamicSharedMemorySize, SMEM_BYTES);

    style_kernel<<<dim3(3, CB), 256>>>(z, ma);
    modw_kernel<<<dim3(3, CB), 256>>>(ma);

    dim3 grid(NN / BN, CC / BM, CB);
    gemm_kernel<0, 1><<<grid, NT, SMEM_BYTES>>>(x, bb[0], out, 0);
    gemm_kernel<1, 2><<<grid, NT, SMEM_BYTES>>>(x, bb[1], out, 1);
    gemm_kernel<2, 0><<<grid, NT, SMEM_BYTES>>>(x, bb[2], out, 2);
}

// round 8
// speedup vs baseline: 2.1721x; 1.3743x over previous
#include <cuda_runtime.h>
#include <cuda_fp16.h>
#include <cstdint>
#include <cstddef>

// ---------------------------------------------------------------------------
// StyledMLP: 3 chained modulated 1x1 convs (B=16, C=256, N=16384, S=512)
// Legacy mma.sync fp16 (tcgen05 unavailable: harness emits compute_103 PTX).
// 2-term split-fp16: W = wh + wl (fp16 hi/lo), X single fp16 plane.
//   y = (wh + wl) @ xh  -> dropped term w*(x-xh) ~ 1.2e-4 rel/layer.
// R7: work = 2/3 of 3-term bf16; activation planes halved.
// ---------------------------------------------------------------------------

#define CB   16
#define CC   256
#define NN   16384
#define SS   512

#define BM 128
#define BN 128
#define BK 32
#define NT 128          // threads per CTA

// scratch (allocation-free rule: __device__ globals)
__device__ __half g_X0[(size_t)CB * CC * NN];    // layer0 out (fp16)
__device__ __half g_X1[(size_t)CB * CC * NN];    // layer1 out (fp16)
__device__ __half g_Whi[3 * CB * CC * CC];
__device__ __half g_Wlo[3 * CB * CC * CC];
__device__ float  g_style[3 * CB * CC];

// ---------------------------------------------------------------------------
// PTX helpers
// ---------------------------------------------------------------------------
__device__ __forceinline__ void cp16(void* sdst, const void* gsrc) {
    unsigned a = (unsigned)__cvta_generic_to_shared(sdst);
    asm volatile("cp.async.cg.shared.global [%0], [%1], 16;\n" :: "r"(a), "l"(gsrc));
}
__device__ __forceinline__ void cp_commit() {
    asm volatile("cp.async.commit_group;\n" ::: "memory");
}
__device__ __forceinline__ void ldsm4(uint32_t* r, const void* p) {
    unsigned a = (unsigned)__cvta_generic_to_shared(p);
    asm volatile("ldmatrix.sync.aligned.m8n8.x4.shared.b16 {%0,%1,%2,%3}, [%4];\n"
                 : "=r"(r[0]), "=r"(r[1]), "=r"(r[2]), "=r"(r[3]) : "r"(a));
}
__device__ __forceinline__ void ldsm4t(uint32_t* r, const void* p) {
    unsigned a = (unsigned)__cvta_generic_to_shared(p);
    asm volatile("ldmatrix.sync.aligned.m8n8.x4.trans.shared.b16 {%0,%1,%2,%3}, [%4];\n"
                 : "=r"(r[0]), "=r"(r[1]), "=r"(r[2]), "=r"(r[3]) : "r"(a));
}
// pack two fp32 -> fp16x2 (low 16 = first/smaller-k element)
__device__ __forceinline__ uint32_t packf16(float lo, float hi) {
    uint32_t r;
    asm("cvt.rn.f16x2.f32 %0, %1, %2;" : "=r"(r) : "f"(hi), "f"(lo));
    return r;
}
__device__ __forceinline__ void mma16816(float* c, const uint32_t* a, uint32_t b0, uint32_t b1) {
    asm volatile("mma.sync.aligned.m16n8k16.row.col.f32.f16.f16.f32 "
                 "{%0,%1,%2,%3}, {%4,%5,%6,%7}, {%8,%9}, {%0,%1,%2,%3};\n"
                 : "+f"(c[0]), "+f"(c[1]), "+f"(c[2]), "+f"(c[3])
                 : "r"(a[0]), "r"(a[1]), "r"(a[2]), "r"(a[3]), "r"(b0), "r"(b1));
}
__device__ __forceinline__ float warp_sum(float v) {
    #pragma unroll
    for (int o = 16; o; o >>= 1) v += __shfl_xor_sync(0xffffffffu, v, o);
    return v;
}

// ---------------------------------------------------------------------------
// Modulation (structure unchanged — measured fast); now emits fp16 hi/lo W.
// ---------------------------------------------------------------------------
struct ModArgs {
    const float* w[3];
    const float* mw[3];
    const float* mb[3];
};

__global__ void style_kernel(const float* __restrict__ z, ModArgs args) {
    int layer = blockIdx.x, b = blockIdx.y;
    int tid = threadIdx.x, warp = tid >> 5, lane = tid & 31;
    __shared__ float zs[SS];
    for (int i = tid; i < SS; i += 256) zs[i] = z[(size_t)b * SS + i];
    __syncthreads();

    const float* mw = args.mw[layer];
    const float* mb = args.mb[layer];
    for (int c = warp; c < CC; c += 8) {
        const float* row = mw + (size_t)c * SS;
        float s = 0.f;
        #pragma unroll
        for (int j = 0; j < SS / 32; j++)
            s = fmaf(row[lane + 32 * j], zs[lane + 32 * j], s);
        s = warp_sum(s);
        if (lane == 0)
            g_style[((size_t)layer * CB + b) * CC + c] =
                s * 0.04419417382415922f + mb[c];
    }
}

__global__ void modw_kernel(ModArgs args) {
    int layer = blockIdx.x, b = blockIdx.y;
    int tid = threadIdx.x, warp = tid >> 5, lane = tid & 31;
    __shared__ float st[CC];
    for (int i = tid; i < CC; i += 256)
        st[i] = g_style[((size_t)layer * CB + b) * CC + i];
    __syncthreads();

    const float* w = args.w[layer];
    __half* oh = g_Whi + ((size_t)(layer * CB + b)) * CC * CC;
    __half* ol = g_Wlo + ((size_t)(layer * CB + b)) * CC * CC;

    for (int r = warp; r < CC; r += 8) {
        const float* wr = w + (size_t)r * CC;
        float s2 = 0.f;
        #pragma unroll
        for (int j = 0; j < CC / 32; j++) {
            float v = wr[lane + 32 * j] * st[lane + 32 * j];
            s2 = fmaf(v, v, s2);
        }
        s2 = warp_sum(s2);
        float ss = s2 * (0.0625f * 0.0625f) + 1e-8f;
        float d = rsqrtf(ss);
        d = d * (1.5f - 0.5f * ss * d * d);          // Newton refine
        float scale = 0.0625f * d;
        #pragma unroll
        for (int j = 0; j < CC / 32; j++) {
            int i = lane + 32 * j;
            float v = wr[i] * st[i] * scale;
            __half h = __float2half_rn(v);
            oh[(size_t)r * CC + i] = h;
            ol[(size_t)r * CC + i] = __float2half_rn(v - __half2float(h));
        }
    }
}

// ---------------------------------------------------------------------------
// GEMM smem layout (per stage, bytes), 2 stages:
//   [0,10240)       W hi : 128 rows x 40 fp16 (32 used + pad)
//   [10240,20480)   W lo
//   [20480,...)     X region:
//       fp32 path (layer0): staging 32 x 132 f32 (pitch 528B) = 16896
//       fp16 path: single plane 32 x 136 fp16 (pitch 272B)    = 8704
// ---------------------------------------------------------------------------
#define WPITCH 40
#define STG_PITCHF 132
#define XP 136
#define PS_F32 37888       // 20480 + 16896, padded to 128
#define PS_F16 29184       // 20480 + 8704
#define SMEM_F32 (2 * PS_F32)
#define SMEM_F16 (2 * PS_F16)

template<int IN_M>  // 0 = fp32 harness x, 1 = g_X0, 2 = g_X1
__device__ __forceinline__ void load_stage(char* sm, int stage,
                                           const __half* gWh,
                                           const __half* gWl,
                                           const float* Xf,
                                           const __half* Xp,
                                           int k0, int n0, int tid) {
    const int PS = (IN_M == 0) ? PS_F32 : PS_F16;
    char* base = sm + stage * PS;
    #pragma unroll
    for (int i = 0; i < 4; i++) {                 // W hi+lo: 128x32 fp16 each
        int c = tid + i * NT;                     // 0..511
        int row = c >> 2, cc = c & 3;
        cp16(base + (row * WPITCH + cc * 8) * 2, gWh + (size_t)row * CC + k0 + cc * 8);
        cp16(base + 10240 + (row * WPITCH + cc * 8) * 2, gWl + (size_t)row * CC + k0 + cc * 8);
    }
    if (IN_M == 0) {
        #pragma unroll
        for (int i = 0; i < 8; i++) {             // X fp32: 32x128
            int c = tid + i * NT;                 // 0..1023
            int row = c >> 5, cc = c & 31;
            cp16(base + 20480 + row * (STG_PITCHF * 4) + cc * 16,
                 Xf + (size_t)(k0 + row) * NN + n0 + cc * 4);
        }
    } else {
        #pragma unroll
        for (int i = 0; i < 4; i++) {             // X fp16: 32x128 single plane
            int c = tid + i * NT;                 // 0..511
            int row = c >> 4, cc = c & 15;
            cp16(base + 20480 + (row * XP + cc * 8) * 2,
                 Xp + (size_t)(k0 + row) * NN + n0 + cc * 8);
        }
    }
}

// ---------------------------------------------------------------------------
// GEMM. CTA 128x128, 4 warps (warp tile 64x64, grid 2x2), K=256,
// 2-stage pipeline, one barrier per chunk, 2-term fp16 MMA.
// OUT_M: 0 = fp32 d_out, 1 = g_X0, 2 = g_X1
// ---------------------------------------------------------------------------
template<int IN_M, int OUT_M>
__global__ void __launch_bounds__(NT, 2)
gemm_kernel(const float* __restrict__ xin, const float* __restrict__ bias,
            float* __restrict__ yout, int layer) {
    extern __shared__ __align__(128) char sm[];
    const int PS = (IN_M == 0) ? PS_F32 : PS_F16;

    const __half* Xp_in = (IN_M == 1) ? g_X0 : g_X1;

    int b  = blockIdx.z;
    int m0 = blockIdx.y * BM;
    int n0 = blockIdx.x * BN;
    int tid  = threadIdx.x;
    int lane = tid & 31;
    int warp = tid >> 5;
    int wm = warp & 1;      // 2 warps along M (64 rows each)
    int wn = warp >> 1;     // 2 warps along N (64 cols each)

    const __half* gWh = g_Whi + ((size_t)(layer * CB + b)) * CC * CC + (size_t)m0 * CC;
    const __half* gWl = g_Wlo + ((size_t)(layer * CB + b)) * CC * CC + (size_t)m0 * CC;
    const float* Xf = (IN_M == 0) ? (xin + (size_t)b * CC * NN) : nullptr;
    const __half* Xp = (IN_M == 0) ? nullptr : Xp_in + (size_t)b * CC * NN;

    float acc[4][8][4];
    #pragma unroll
    for (int i = 0; i < 4; i++)
        #pragma unroll
        for (int j = 0; j < 8; j++)
            #pragma unroll
            for (int k = 0; k < 4; k++) acc[i][j][k] = 0.f;

    load_stage<IN_M>(sm, 0, gWh, gWl, Xf, Xp, 0, n0, tid);
    cp_commit();

    #pragma unroll 1
    for (int ch = 0; ch < 8; ch++) {
        int stage = ch & 1;
        asm volatile("cp.async.wait_group 0;\n" ::: "memory");
        __syncthreads();   // stage data visible; stage^1 readers (chunk ch-1) done

        if (ch < 7) {
            load_stage<IN_M>(sm, stage ^ 1, gWh, gWl, Xf, Xp, (ch + 1) * BK, n0, tid);
            cp_commit();
        }

        char* base = sm + stage * PS;
        const __half* Whi = (const __half*)base;
        const __half* Wlo = (const __half*)(base + 10240);

        #pragma unroll
        for (int kk = 0; kk < BK; kk += 16) {
            uint32_t ah[4][4], al[4][4];
            #pragma unroll
            for (int mt = 0; mt < 4; mt++) {
                int row = wm * 64 + mt * 16 + (lane & 15);
                int col = kk + ((lane >> 4) << 3);
                ldsm4(ah[mt], &Whi[row * WPITCH + col]);
                ldsm4(al[mt], &Wlo[row * WPITCH + col]);
            }
            if (IN_M == 0) {
                const float* Xst = (const float*)(base + 20480);
                #pragma unroll
                for (int nt = 0; nt < 8; nt++) {
                    int n  = wn * 64 + nt * 8 + (lane >> 2);
                    int kb = kk + 2 * (lane & 3);
                    const float* xp = Xst + kb * STG_PITCHF + n;
                    uint32_t b0 = packf16(xp[0], xp[STG_PITCHF]);
                    uint32_t b1 = packf16(xp[8 * STG_PITCHF], xp[9 * STG_PITCHF]);
                    #pragma unroll
                    for (int mt = 0; mt < 4; mt++) mma16816(acc[mt][nt], ah[mt], b0, b1);
                    #pragma unroll
                    for (int mt = 0; mt < 4; mt++) mma16816(acc[mt][nt], al[mt], b0, b1);
                }
            } else {
                const __half* sX = (const __half*)(base + 20480);
                uint32_t bh[4][4];
                #pragma unroll
                for (int c2 = 0; c2 < 4; c2++) {
                    int k = kk + ((lane >> 3) & 1) * 8 + (lane & 7);
                    int n = wn * 64 + c2 * 16 + (lane >> 4) * 8;
                    ldsm4t(bh[c2], &sX[k * XP + n]);
                }
                #pragma unroll
                for (int nt = 0; nt < 8; nt++) {
                    int c2 = nt >> 1, sub = (nt & 1) * 2;
                    #pragma unroll
                    for (int mt = 0; mt < 4; mt++)
                        mma16816(acc[mt][nt], ah[mt], bh[c2][sub], bh[c2][sub + 1]);
                }
                #pragma unroll
                for (int nt = 0; nt < 8; nt++) {
                    int c2 = nt >> 1, sub = (nt & 1) * 2;
                    #pragma unroll
                    for (int mt = 0; mt < 4; mt++)
                        mma16816(acc[mt][nt], al[mt], bh[c2][sub], bh[c2][sub + 1]);
                }
            }
        }
    }

    // epilogue: bias + leaky(0.2) * sqrt(2); write fp32 or single fp16 plane
    const float S2 = 1.4142135623730951f;
    __half* Yp = (OUT_M == 1) ? g_X0 : g_X1;
    float* Yf = (OUT_M == 0) ? (yout + (size_t)b * CC * NN) : nullptr;
    if (OUT_M != 0) Yp += (size_t)b * CC * NN;

    #pragma unroll
    for (int mt = 0; mt < 4; mt++) {
        int r0 = m0 + wm * 64 + mt * 16 + (lane >> 2);
        float bv0 = __ldg(&bias[r0]);
        float bv1 = __ldg(&bias[r0 + 8]);
        #pragma unroll
        for (int nt = 0; nt < 8; nt++) {
            int cidx = n0 + wn * 64 + nt * 8 + 2 * (lane & 3);
            float y0 = acc[mt][nt][0] + bv0;
            float y1 = acc[mt][nt][1] + bv0;
            float y2 = acc[mt][nt][2] + bv1;
            float y3 = acc[mt][nt][3] + bv1;
            y0 = (y0 >= 0.f ? y0 : 0.2f * y0) * S2;
            y1 = (y1 >= 0.f ? y1 : 0.2f * y1) * S2;
            y2 = (y2 >= 0.f ? y2 : 0.2f * y2) * S2;
            y3 = (y3 >= 0.f ? y3 : 0.2f * y3) * S2;
            if (OUT_M == 0) {
                *(float2*)(Yf + (size_t)r0 * NN + cidx)       = make_float2(y0, y1);
                *(float2*)(Yf + (size_t)(r0 + 8) * NN + cidx) = make_float2(y2, y3);
            } else {
                __half2 p0; p0.x = __float2half_rn(y0); p0.y = __float2half_rn(y1);
                __half2 p1; p1.x = __float2half_rn(y2); p1.y = __float2half_rn(y3);
                *(__half2*)(Yp + (size_t)r0 * NN + cidx)       = p0;
                *(__half2*)(Yp + (size_t)(r0 + 8) * NN + cidx) = p1;
            }
        }
    }
}

// ---------------------------------------------------------------------------
extern "C" void kernel_launch(void* const* d_in, const int* in_sizes, int n_in,
                              void* d_out, int out_size) {
    (void)in_sizes; (void)n_in; (void)out_size;
    const float* x = (const float*)d_in[0];
    const float* z = (const float*)d_in[1];
    ModArgs ma;
    const float* bb[3];
    for (int l = 0; l < 3; l++) {
        ma.w[l]  = (const float*)d_in[2 + 4 * l];
        ma.mw[l] = (const float*)d_in[3 + 4 * l];
        ma.mb[l] = (const float*)d_in[4 + 4 * l];
        bb[l]    = (const float*)d_in[5 + 4 * l];
    }
    float* out = (float*)d_out;

    cudaFuncSetAttribute(gemm_kernel<0, 1>, cudaFuncAttributeMaxDynamicSharedMemorySize, SMEM_F32);
    cudaFuncSetAttribute(gemm_kernel<1, 2>, cudaFuncAttributeMaxDynamicSharedMemorySize, SMEM_F16);
    cudaFuncSetAttribute(gemm_kernel<2, 0>, cudaFuncAttributeMaxDynamicSharedMemorySize, SMEM_F16);

    style_kernel<<<dim3(3, CB), 256>>>(z, ma);
    modw_kernel<<<dim3(3, CB), 256>>>(ma);

    dim3 grid(NN / BN, CC / BM, CB);
    gemm_kernel<0, 1><<<grid, NT, SMEM_F32>>>(x, bb[0], out, 0);
    gemm_kernel<1, 2><<<grid, NT, SMEM_F16>>>(x, bb[1], out, 1);
    gemm_kernel<2, 0><<<grid, NT, SMEM_F16>>>(x, bb[2], out, 2);
}

// round 12
// speedup vs baseline: 2.6180x; 1.2053x over previous
#include <cuda_runtime.h>
#include <cuda_fp16.h>
#include <cstdint>
#include <cstddef>

// ---------------------------------------------------------------------------
// StyledMLP: 3 chained modulated 1x1 convs (B=16, C=256, N=16384, S=512)
// Legacy mma.sync fp16 single-term (tcgen05 unavailable on this harness).
//   y = w_fp16 @ x_fp16 ; fp32 accumulate.
// R9: R8 with device-global pointers selected INSIDE the kernel (template
// selector) — R8 passed __device__ symbols as host args (invalid addresses).
// ---------------------------------------------------------------------------

#define CB   16
#define CC   256
#define NN   16384
#define SS   512

#define BM 128
#define BN 128
#define BK 32
#define NT 128          // threads per CTA

// scratch (allocation-free rule: __device__ globals)
__device__ __half g_Xin[(size_t)CB * CC * NN];   // converted input
__device__ __half g_X0[(size_t)CB * CC * NN];    // layer0 out
__device__ __half g_X1[(size_t)CB * CC * NN];    // layer1 out
__device__ __half g_W[3 * CB * CC * CC];         // modulated fp16 weights
__device__ float  g_style[3 * CB * CC];

// ---------------------------------------------------------------------------
// PTX helpers
// ---------------------------------------------------------------------------
__device__ __forceinline__ void cp16(void* sdst, const void* gsrc) {
    unsigned a = (unsigned)__cvta_generic_to_shared(sdst);
    asm volatile("cp.async.cg.shared.global [%0], [%1], 16;\n" :: "r"(a), "l"(gsrc));
}
__device__ __forceinline__ void cp_commit() {
    asm volatile("cp.async.commit_group;\n" ::: "memory");
}
__device__ __forceinline__ void ldsm4(uint32_t* r, const void* p) {
    unsigned a = (unsigned)__cvta_generic_to_shared(p);
    asm volatile("ldmatrix.sync.aligned.m8n8.x4.shared.b16 {%0,%1,%2,%3}, [%4];\n"
                 : "=r"(r[0]), "=r"(r[1]), "=r"(r[2]), "=r"(r[3]) : "r"(a));
}
__device__ __forceinline__ void ldsm4t(uint32_t* r, const void* p) {
    unsigned a = (unsigned)__cvta_generic_to_shared(p);
    asm volatile("ldmatrix.sync.aligned.m8n8.x4.trans.shared.b16 {%0,%1,%2,%3}, [%4];\n"
                 : "=r"(r[0]), "=r"(r[1]), "=r"(r[2]), "=r"(r[3]) : "r"(a));
}
__device__ __forceinline__ void mma16816(float* c, const uint32_t* a, uint32_t b0, uint32_t b1) {
    asm volatile("mma.sync.aligned.m16n8k16.row.col.f32.f16.f16.f32 "
                 "{%0,%1,%2,%3}, {%4,%5,%6,%7}, {%8,%9}, {%0,%1,%2,%3};\n"
                 : "+f"(c[0]), "+f"(c[1]), "+f"(c[2]), "+f"(c[3])
                 : "r"(a[0]), "r"(a[1]), "r"(a[2]), "r"(a[3]), "r"(b0), "r"(b1));
}
__device__ __forceinline__ float warp_sum(float v) {
    #pragma unroll
    for (int o = 16; o; o >>= 1) v += __shfl_xor_sync(0xffffffffu, v, o);
    return v;
}

// ---------------------------------------------------------------------------
// Input conversion: x fp32 -> g_Xin fp16 (vectorized, one shot)
// ---------------------------------------------------------------------------
__global__ void cvt_kernel(const float* __restrict__ x) {
    size_t i = ((size_t)blockIdx.x * 256 + threadIdx.x) * 4;
    float4 v = *(const float4*)(x + i);
    __half2 p0 = __floats2half2_rn(v.x, v.y);
    __half2 p1 = __floats2half2_rn(v.z, v.w);
    uint2 u;
    u.x = *(uint32_t*)&p0;
    u.y = *(uint32_t*)&p1;
    *(uint2*)(g_Xin + i) = u;
}

// ---------------------------------------------------------------------------
// Modulation (structure unchanged — measured fast); emits single fp16 W.
// ---------------------------------------------------------------------------
struct ModArgs {
    const float* w[3];
    const float* mw[3];
    const float* mb[3];
};

__global__ void style_kernel(const float* __restrict__ z, ModArgs args) {
    int layer = blockIdx.x, b = blockIdx.y;
    int tid = threadIdx.x, warp = tid >> 5, lane = tid & 31;
    __shared__ float zs[SS];
    for (int i = tid; i < SS; i += 256) zs[i] = z[(size_t)b * SS + i];
    __syncthreads();

    const float* mw = args.mw[layer];
    const float* mb = args.mb[layer];
    for (int c = warp; c < CC; c += 8) {
        const float* row = mw + (size_t)c * SS;
        float s = 0.f;
        #pragma unroll
        for (int j = 0; j < SS / 32; j++)
            s = fmaf(row[lane + 32 * j], zs[lane + 32 * j], s);
        s = warp_sum(s);
        if (lane == 0)
            g_style[((size_t)layer * CB + b) * CC + c] =
                s * 0.04419417382415922f + mb[c];
    }
}

__global__ void modw_kernel(ModArgs args) {
    int layer = blockIdx.x, b = blockIdx.y;
    int tid = threadIdx.x, warp = tid >> 5, lane = tid & 31;
    __shared__ float st[CC];
    for (int i = tid; i < CC; i += 256)
        st[i] = g_style[((size_t)layer * CB + b) * CC + i];
    __syncthreads();

    const float* w = args.w[layer];
    __half* ow = g_W + ((size_t)(layer * CB + b)) * CC * CC;

    for (int r = warp; r < CC; r += 8) {
        const float* wr = w + (size_t)r * CC;
        float s2 = 0.f;
        #pragma unroll
        for (int j = 0; j < CC / 32; j++) {
            float v = wr[lane + 32 * j] * st[lane + 32 * j];
            s2 = fmaf(v, v, s2);
        }
        s2 = warp_sum(s2);
        float ss = s2 * (0.0625f * 0.0625f) + 1e-8f;
        float d = rsqrtf(ss);
        d = d * (1.5f - 0.5f * ss * d * d);          // Newton refine
        float scale = 0.0625f * d;
        #pragma unroll
        for (int j = 0; j < CC / 32; j++) {
            int i = lane + 32 * j;
            ow[(size_t)r * CC + i] = __float2half_rn(wr[i] * st[i] * scale);
        }
    }
}

// ---------------------------------------------------------------------------
// GEMM smem layout (per stage, bytes), 2 stages:
//   [0,10240)       W : 128 rows x 40 fp16 (32 used + pad)
//   [10240,18944)   X : 32 rows x 136 fp16 (128 used + pad)
// ---------------------------------------------------------------------------
#define WPITCH 40
#define XP 136
#define PS 18944
#define SMEM_BYTES (2 * PS)

__device__ __forceinline__ void load_stage(char* sm, int stage,
                                           const __half* gW,
                                           const __half* Xp,
                                           int k0, int n0, int tid) {
    char* base = sm + stage * PS;
    #pragma unroll
    for (int i = 0; i < 4; i++) {                 // W: 128x32 fp16
        int c = tid + i * NT;                     // 0..511
        int row = c >> 2, cc = c & 3;
        cp16(base + (row * WPITCH + cc * 8) * 2, gW + (size_t)row * CC + k0 + cc * 8);
    }
    #pragma unroll
    for (int i = 0; i < 4; i++) {                 // X: 32x128 fp16
        int c = tid + i * NT;                     // 0..511
        int row = c >> 4, cc = c & 15;
        cp16(base + 10240 + (row * XP + cc * 8) * 2,
             Xp + (size_t)(k0 + row) * NN + n0 + cc * 8);
    }
}

// ---------------------------------------------------------------------------
// GEMM. CTA 128x128, 4 warps (warp tile 64x64, grid 2x2), K=256,
// 2-stage pipeline, one barrier per chunk, single fp16 MMA term.
// IN_SEL: 0 = g_Xin, 1 = g_X0, 2 = g_X1  (resolved in DEVICE code)
// OUT_SEL: 0 = fp32 harness out, 1 = g_X0, 2 = g_X1
// ---------------------------------------------------------------------------
template<int IN_SEL, int OUT_SEL>
__global__ void __launch_bounds__(NT, 2)
gemm_kernel(const float* __restrict__ bias, float* __restrict__ yout, int layer) {
    extern __shared__ __align__(128) char sm[];

    const __half* Xin = (IN_SEL == 0) ? g_Xin : (IN_SEL == 1 ? g_X0 : g_X1);

    int b  = blockIdx.z;
    int m0 = blockIdx.y * BM;
    int n0 = blockIdx.x * BN;
    int tid  = threadIdx.x;
    int lane = tid & 31;
    int warp = tid >> 5;
    int wm = warp & 1;      // 2 warps along M (64 rows each)
    int wn = warp >> 1;     // 2 warps along N (64 cols each)

    const __half* gW = g_W + ((size_t)(layer * CB + b)) * CC * CC + (size_t)m0 * CC;
    const __half* Xp = Xin + (size_t)b * CC * NN;

    float acc[4][8][4];
    #pragma unroll
    for (int i = 0; i < 4; i++)
        #pragma unroll
        for (int j = 0; j < 8; j++)
            #pragma unroll
            for (int k = 0; k < 4; k++) acc[i][j][k] = 0.f;

    load_stage(sm, 0, gW, Xp, 0, n0, tid);
    cp_commit();

    #pragma unroll 1
    for (int ch = 0; ch < 8; ch++) {
        int stage = ch & 1;
        asm volatile("cp.async.wait_group 0;\n" ::: "memory");
        __syncthreads();   // stage data visible; stage^1 readers (chunk ch-1) done

        if (ch < 7) {
            load_stage(sm, stage ^ 1, gW, Xp, (ch + 1) * BK, n0, tid);
            cp_commit();
        }

        char* base = sm + stage * PS;
        const __half* Ws = (const __half*)base;
        const __half* Xs = (const __half*)(base + 10240);

        #pragma unroll
        for (int kk = 0; kk < BK; kk += 16) {
            uint32_t ah[4][4];
            #pragma unroll
            for (int mt = 0; mt < 4; mt++) {
                int row = wm * 64 + mt * 16 + (lane & 15);
                int col = kk + ((lane >> 4) << 3);
                ldsm4(ah[mt], &Ws[row * WPITCH + col]);
            }
            uint32_t bh[4][4];
            #pragma unroll
            for (int c2 = 0; c2 < 4; c2++) {
                int k = kk + ((lane >> 3) & 1) * 8 + (lane & 7);
                int n = wn * 64 + c2 * 16 + (lane >> 4) * 8;
                ldsm4t(bh[c2], &Xs[k * XP + n]);
            }
            #pragma unroll
            for (int nt = 0; nt < 8; nt++) {
                int c2 = nt >> 1, sub = (nt & 1) * 2;
                #pragma unroll
                for (int mt = 0; mt < 4; mt++)
                    mma16816(acc[mt][nt], ah[mt], bh[c2][sub], bh[c2][sub + 1]);
            }
        }
    }

    // epilogue: bias + leaky(0.2) * sqrt(2)
    const float S2 = 1.4142135623730951f;
    float* Yf = yout + (size_t)b * CC * NN;
    __half* Yp = ((OUT_SEL == 1) ? g_X0 : g_X1) + (size_t)b * CC * NN;

    #pragma unroll
    for (int mt = 0; mt < 4; mt++) {
        int r0 = m0 + wm * 64 + mt * 16 + (lane >> 2);
        float bv0 = __ldg(&bias[r0]);
        float bv1 = __ldg(&bias[r0 + 8]);
        #pragma unroll
        for (int nt = 0; nt < 8; nt++) {
            int cidx = n0 + wn * 64 + nt * 8 + 2 * (lane & 3);
            float y0 = acc[mt][nt][0] + bv0;
            float y1 = acc[mt][nt][1] + bv0;
            float y2 = acc[mt][nt][2] + bv1;
            float y3 = acc[mt][nt][3] + bv1;
            y0 = (y0 >= 0.f ? y0 : 0.2f * y0) * S2;
            y1 = (y1 >= 0.f ? y1 : 0.2f * y1) * S2;
            y2 = (y2 >= 0.f ? y2 : 0.2f * y2) * S2;
            y3 = (y3 >= 0.f ? y3 : 0.2f * y3) * S2;
            if (OUT_SEL == 0) {
                *(float2*)(Yf + (size_t)r0 * NN + cidx)       = make_float2(y0, y1);
                *(float2*)(Yf + (size_t)(r0 + 8) * NN + cidx) = make_float2(y2, y3);
            } else {
                __half2 p0; p0.x = __float2half_rn(y0); p0.y = __float2half_rn(y1);
                __half2 p1; p1.x = __float2half_rn(y2); p1.y = __float2half_rn(y3);
                *(__half2*)(Yp + (size_t)r0 * NN + cidx)       = p0;
                *(__half2*)(Yp + (size_t)(r0 + 8) * NN + cidx) = p1;
            }
        }
    }
}

// ---------------------------------------------------------------------------
extern "C" void kernel_launch(void* const* d_in, const int* in_sizes, int n_in,
                              void* d_out, int out_size) {
    (void)in_sizes; (void)n_in; (void)out_size;
    const float* x = (const float*)d_in[0];
    const float* z = (const float*)d_in[1];
    ModArgs ma;
    const float* bb[3];
    for (int l = 0; l < 3; l++) {
        ma.w[l]  = (const float*)d_in[2 + 4 * l];
        ma.mw[l] = (const float*)d_in[3 + 4 * l];
        ma.mb[l] = (const float*)d_in[4 + 4 * l];
        bb[l]    = (const float*)d_in[5 + 4 * l];
    }
    float* out = (float*)d_out;

    cudaFuncSetAttribute(gemm_kernel<0, 1>, cudaFuncAttributeMaxDynamicSharedMemorySize, SMEM_BYTES);
    cudaFuncSetAttribute(gemm_kernel<1, 2>, cudaFuncAttributeMaxDynamicSharedMemorySize, SMEM_BYTES);
    cudaFuncSetAttribute(gemm_kernel<2, 0>, cudaFuncAttributeMaxDynamicSharedMemorySize, SMEM_BYTES);

    // input conversion + modulation (independent; all graph-capturable launches)
    cvt_kernel<<<(unsigned)((size_t)CB * CC * NN / (256 * 4)), 256>>>(x);
    style_kernel<<<dim3(3, CB), 256>>>(z, ma);
    modw_kernel<<<dim3(3, CB), 256>>>(ma);

    dim3 grid(NN / BN, CC / BM, CB);
    gemm_kernel<0, 1><<<grid, NT, SMEM_BYTES>>>(bb[0], out, 0);
    gemm_kernel<1, 2><<<grid, NT, SMEM_BYTES>>>(bb[1], out, 1);
    gemm_kernel<2, 0><<<grid, NT, SMEM_BYTES>>>(bb[2], out, 2);
}

// round 13
// speedup vs baseline: 2.6385x; 1.0078x over previous
#include <cuda_runtime.h>
#include <cuda_fp16.h>
#include <cstdint>
#include <cstddef>

// ---------------------------------------------------------------------------
// StyledMLP: 3 chained modulated 1x1 convs (B=16, C=256, N=16384, S=512)
// Legacy mma.sync fp16 single-term; fp32 accumulate.
// R10: 256 thr / 8 warps per CTA, warp tile 32x64 (acc 64 regs) -> 16 warps/SM
// (4 per SMSP) to hide LDSM/dependency latency exposed at occ 12%.
// ---------------------------------------------------------------------------

#define CB   16
#define CC   256
#define NN   16384
#define SS   512

#define BM 128
#define BN 128
#define BK 32
#define NT 256          // threads per CTA

// scratch (allocation-free rule: __device__ globals)
__device__ __half g_Xin[(size_t)CB * CC * NN];   // converted input
__device__ __half g_X0[(size_t)CB * CC * NN];    // layer0 out
__device__ __half g_X1[(size_t)CB * CC * NN];    // layer1 out
__device__ __half g_W[3 * CB * CC * CC];         // modulated fp16 weights
__device__ float  g_style[3 * CB * CC];

// ---------------------------------------------------------------------------
// PTX helpers
// ---------------------------------------------------------------------------
__device__ __forceinline__ void cp16(void* sdst, const void* gsrc) {
    unsigned a = (unsigned)__cvta_generic_to_shared(sdst);
    asm volatile("cp.async.cg.shared.global [%0], [%1], 16;\n" :: "r"(a), "l"(gsrc));
}
__device__ __forceinline__ void cp_commit() {
    asm volatile("cp.async.commit_group;\n" ::: "memory");
}
__device__ __forceinline__ void ldsm4(uint32_t* r, const void* p) {
    unsigned a = (unsigned)__cvta_generic_to_shared(p);
    asm volatile("ldmatrix.sync.aligned.m8n8.x4.shared.b16 {%0,%1,%2,%3}, [%4];\n"
                 : "=r"(r[0]), "=r"(r[1]), "=r"(r[2]), "=r"(r[3]) : "r"(a));
}
__device__ __forceinline__ void ldsm4t(uint32_t* r, const void* p) {
    unsigned a = (unsigned)__cvta_generic_to_shared(p);
    asm volatile("ldmatrix.sync.aligned.m8n8.x4.trans.shared.b16 {%0,%1,%2,%3}, [%4];\n"
                 : "=r"(r[0]), "=r"(r[1]), "=r"(r[2]), "=r"(r[3]) : "r"(a));
}
__device__ __forceinline__ void mma16816(float* c, const uint32_t* a0, const uint32_t* a1,
                                         uint32_t b0, uint32_t b1) {
    asm volatile("mma.sync.aligned.m16n8k16.row.col.f32.f16.f16.f32 "
                 "{%0,%1,%2,%3}, {%4,%5,%6,%7}, {%8,%9}, {%0,%1,%2,%3};\n"
                 : "+f"(c[0]), "+f"(c[1]), "+f"(c[2]), "+f"(c[3])
                 : "r"(a0[0]), "r"(a0[1]), "r"(a1[0]), "r"(a1[1]), "r"(b0), "r"(b1));
}
__device__ __forceinline__ float warp_sum(float v) {
    #pragma unroll
    for (int o = 16; o; o >>= 1) v += __shfl_xor_sync(0xffffffffu, v, o);
    return v;
}

// ---------------------------------------------------------------------------
// Input conversion: x fp32 -> g_Xin fp16 (vectorized, one shot)
// ---------------------------------------------------------------------------
__global__ void cvt_kernel(const float* __restrict__ x) {
    size_t i = ((size_t)blockIdx.x * 256 + threadIdx.x) * 4;
    float4 v = *(const float4*)(x + i);
    __half2 p0 = __floats2half2_rn(v.x, v.y);
    __half2 p1 = __floats2half2_rn(v.z, v.w);
    uint2 u;
    u.x = *(uint32_t*)&p0;
    u.y = *(uint32_t*)&p1;
    *(uint2*)(g_Xin + i) = u;
}

// ---------------------------------------------------------------------------
// Modulation
// ---------------------------------------------------------------------------
struct ModArgs {
    const float* w[3];
    const float* mw[3];
    const float* mb[3];
};

__global__ void style_kernel(const float* __restrict__ z, ModArgs args) {
    int layer = blockIdx.x, b = blockIdx.y;
    int tid = threadIdx.x, warp = tid >> 5, lane = tid & 31;
    __shared__ float zs[SS];
    for (int i = tid; i < SS; i += 256) zs[i] = z[(size_t)b * SS + i];
    __syncthreads();

    const float* mw = args.mw[layer];
    const float* mb = args.mb[layer];
    for (int c = warp; c < CC; c += 8) {
        const float* row = mw + (size_t)c * SS;
        float s = 0.f;
        #pragma unroll
        for (int j = 0; j < SS / 32; j++)
            s = fmaf(row[lane + 32 * j], zs[lane + 32 * j], s);
        s = warp_sum(s);
        if (lane == 0)
            g_style[((size_t)layer * CB + b) * CC + c] =
                s * 0.04419417382415922f + mb[c];
    }
}

// grid (3, CB, 8): each block handles 32 rows -> 384 blocks (was 48)
__global__ void modw_kernel(ModArgs args) {
    int layer = blockIdx.x, b = blockIdx.y, rg = blockIdx.z;
    int tid = threadIdx.x, warp = tid >> 5, lane = tid & 31;
    __shared__ float st[CC];
    for (int i = tid; i < CC; i += 256)
        st[i] = g_style[((size_t)layer * CB + b) * CC + i];
    __syncthreads();

    const float* w = args.w[layer];
    __half* ow = g_W + ((size_t)(layer * CB + b)) * CC * CC;

    for (int r = rg * 32 + warp; r < rg * 32 + 32; r += 8) {
        const float* wr = w + (size_t)r * CC;
        float s2 = 0.f;
        #pragma unroll
        for (int j = 0; j < CC / 32; j++) {
            float v = wr[lane + 32 * j] * st[lane + 32 * j];
            s2 = fmaf(v, v, s2);
        }
        s2 = warp_sum(s2);
        float ss = s2 * (0.0625f * 0.0625f) + 1e-8f;
        float d = rsqrtf(ss);
        d = d * (1.5f - 0.5f * ss * d * d);          // Newton refine
        float scale = 0.0625f * d;
        #pragma unroll
        for (int j = 0; j < CC / 32; j++) {
            int i = lane + 32 * j;
            ow[(size_t)r * CC + i] = __float2half_rn(wr[i] * st[i] * scale);
        }
    }
}

// ---------------------------------------------------------------------------
// GEMM smem layout (per stage, bytes), 2 stages:
//   [0,10240)       W : 128 rows x 40 fp16 (32 used + pad)
//   [10240,18944)   X : 32 rows x 136 fp16 (128 used + pad)
// ---------------------------------------------------------------------------
#define WPITCH 40
#define XP 136
#define PS 18944
#define SMEM_BYTES (2 * PS)

__device__ __forceinline__ void load_stage(char* sm, int stage,
                                           const __half* gW,
                                           const __half* Xp,
                                           int k0, int n0, int tid) {
    char* base = sm + stage * PS;
    #pragma unroll
    for (int i = 0; i < 2; i++) {                 // W: 128x32 fp16
        int c = tid + i * NT;                     // 0..511
        int row = c >> 2, cc = c & 3;
        cp16(base + (row * WPITCH + cc * 8) * 2, gW + (size_t)row * CC + k0 + cc * 8);
    }
    #pragma unroll
    for (int i = 0; i < 2; i++) {                 // X: 32x128 fp16
        int c = tid + i * NT;                     // 0..511
        int row = c >> 4, cc = c & 15;
        cp16(base + 10240 + (row * XP + cc * 8) * 2,
             Xp + (size_t)(k0 + row) * NN + n0 + cc * 8);
    }
}

// ---------------------------------------------------------------------------
// GEMM. CTA 128x128, 8 warps (warp tile 32x64, grid 4Mx2N), K=256,
// 2-stage pipeline, one barrier per chunk, single fp16 MMA term.
// IN_SEL: 0 = g_Xin, 1 = g_X0, 2 = g_X1  (resolved in DEVICE code)
// OUT_SEL: 0 = fp32 harness out, 1 = g_X0, 2 = g_X1
// ---------------------------------------------------------------------------
template<int IN_SEL, int OUT_SEL>
__global__ void __launch_bounds__(NT, 2)
gemm_kernel(const float* __restrict__ bias, float* __restrict__ yout, int layer) {
    extern __shared__ __align__(128) char sm[];

    const __half* Xin = (IN_SEL == 0) ? g_Xin : (IN_SEL == 1 ? g_X0 : g_X1);

    int b  = blockIdx.z;
    int m0 = blockIdx.y * BM;
    int n0 = blockIdx.x * BN;
    int tid  = threadIdx.x;
    int lane = tid & 31;
    int warp = tid >> 5;
    int wm = warp & 3;      // 4 warps along M (32 rows each)
    int wn = warp >> 2;     // 2 warps along N (64 cols each)

    const __half* gW = g_W + ((size_t)(layer * CB + b)) * CC * CC + (size_t)m0 * CC;
    const __half* Xp = Xin + (size_t)b * CC * NN;

    float acc[2][8][4];
    #pragma unroll
    for (int i = 0; i < 2; i++)
        #pragma unroll
        for (int j = 0; j < 8; j++)
            #pragma unroll
            for (int k = 0; k < 4; k++) acc[i][j][k] = 0.f;

    load_stage(sm, 0, gW, Xp, 0, n0, tid);
    cp_commit();

    #pragma unroll 1
    for (int ch = 0; ch < 8; ch++) {
        int stage = ch & 1;
        asm volatile("cp.async.wait_group 0;\n" ::: "memory");
        __syncthreads();   // stage data visible; stage^1 readers (chunk ch-1) done

        if (ch < 7) {
            load_stage(sm, stage ^ 1, gW, Xp, (ch + 1) * BK, n0, tid);
            cp_commit();
        }

        char* base = sm + stage * PS;
        const __half* Ws = (const __half*)base;
        const __half* Xs = (const __half*)(base + 10240);

        #pragma unroll
        for (int kk = 0; kk < BK; kk += 16) {
            uint32_t ah[2][4];                    // 32 rows = 2 x ldsm4
            #pragma unroll
            for (int mt = 0; mt < 2; mt++) {
                int row = wm * 32 + mt * 16 + (lane & 15);
                int col = kk + ((lane >> 4) << 3);
                ldsm4(ah[mt], &Ws[row * WPITCH + col]);
            }
            uint32_t bh[4][4];
            #pragma unroll
            for (int c2 = 0; c2 < 4; c2++) {
                int k = kk + ((lane >> 3) & 1) * 8 + (lane & 7);
                int n = wn * 64 + c2 * 16 + (lane >> 4) * 8;
                ldsm4t(bh[c2], &Xs[k * XP + n]);
            }
            #pragma unroll
            for (int nt = 0; nt < 8; nt++) {
                int c2 = nt >> 1, sub = (nt & 1) * 2;
                #pragma unroll
                for (int mt = 0; mt < 2; mt++)
                    mma16816(acc[mt][nt], &ah[mt][0], &ah[mt][2],
                             bh[c2][sub], bh[c2][sub + 1]);
            }
        }
    }

    // epilogue: bias + leaky(0.2) * sqrt(2)
    const float S2 = 1.4142135623730951f;
    float* Yf = yout + (size_t)b * CC * NN;
    __half* Yp = ((OUT_SEL == 1) ? g_X0 : g_X1) + (size_t)b * CC * NN;

    #pragma unroll
    for (int mt = 0; mt < 2; mt++) {
        int r0 = m0 + wm * 32 + mt * 16 + (lane >> 2);
        float bv0 = __ldg(&bias[r0]);
        float bv1 = __ldg(&bias[r0 + 8]);
        #pragma unroll
        for (int nt = 0; nt < 8; nt++) {
            int cidx = n0 + wn * 64 + nt * 8 + 2 * (lane & 3);
            float y0 = acc[mt][nt][0] + bv0;
            float y1 = acc[mt][nt][1] + bv0;
            float y2 = acc[mt][nt][2] + bv1;
            float y3 = acc[mt][nt][3] + bv1;
            y0 = (y0 >= 0.f ? y0 : 0.2f * y0) * S2;
            y1 = (y1 >= 0.f ? y1 : 0.2f * y1) * S2;
            y2 = (y2 >= 0.f ? y2 : 0.2f * y2) * S2;
            y3 = (y3 >= 0.f ? y3 : 0.2f * y3) * S2;
            if (OUT_SEL == 0) {
                *(float2*)(Yf + (size_t)r0 * NN + cidx)       = make_float2(y0, y1);
                *(float2*)(Yf + (size_t)(r0 + 8) * NN + cidx) = make_float2(y2, y3);
            } else {
                __half2 p0; p0.x = __float2half_rn(y0); p0.y = __float2half_rn(y1);
                __half2 p1; p1.x = __float2half_rn(y2); p1.y = __float2half_rn(y3);
                *(__half2*)(Yp + (size_t)r0 * NN + cidx)       = p0;
                *(__half2*)(Yp + (size_t)(r0 + 8) * NN + cidx) = p1;
            }
        }
    }
}

// ---------------------------------------------------------------------------
extern "C" void kernel_launch(void* const* d_in, const int* in_sizes, int n_in,
                              void* d_out, int out_size) {
    (void)in_sizes; (void)n_in; (void)out_size;
    const float* x = (const float*)d_in[0];
    const float* z = (const float*)d_in[1];
    ModArgs ma;
    const float* bb[3];
    for (int l = 0; l < 3; l++) {
        ma.w[l]  = (const float*)d_in[2 + 4 * l];
        ma.mw[l] = (const float*)d_in[3 + 4 * l];
        ma.mb[l] = (const float*)d_in[4 + 4 * l];
        bb[l]    = (const float*)d_in[5 + 4 * l];
    }
    float* out = (float*)d_out;

    cudaFuncSetAttribute(gemm_kernel<0, 1>, cudaFuncAttributeMaxDynamicSharedMemorySize, SMEM_BYTES);
    cudaFuncSetAttribute(gemm_kernel<1, 2>, cudaFuncAttributeMaxDynamicSharedMemorySize, SMEM_BYTES);
    cudaFuncSetAttribute(gemm_kernel<2, 0>, cudaFuncAttributeMaxDynamicSharedMemorySize, SMEM_BYTES);

    cvt_kernel<<<(unsigned)((size_t)CB * CC * NN / (256 * 4)), 256>>>(x);
    style_kernel<<<dim3(3, CB), 256>>>(z, ma);
    modw_kernel<<<dim3(3, CB, 8), 256>>>(ma);

    dim3 grid(NN / BN, CC / BM, CB);
    gemm_kernel<0, 1><<<grid, NT, SMEM_BYTES>>>(bb[0], out, 0);
    gemm_kernel<1, 2><<<grid, NT, SMEM_BYTES>>>(bb[1], out, 1);
    gemm_kernel<2, 0><<<grid, NT, SMEM_BYTES>>>(bb[2], out, 2);
}